// round 2
// baseline (speedup 1.0000x reference)
#include <cuda_runtime.h>
#include <math.h>

#define N_NODES 32768
#define E_EDGES 524288
#define E_TOT   (E_EDGES + N_NODES)
#define B_GR    64
#define NPG     512
#define DHID    256   // HEADS*HID
#define NHEAD   4
#define HIDC    64
#define D_IN    128
#define D_OUT   128

// ---------------- scratch (device globals; no runtime allocation) ----------------
__device__ float g_h    [(size_t)N_NODES*256];
__device__ float g_x1   [(size_t)N_NODES*256];
__device__ float g_x2   [(size_t)N_NODES*256];
__device__ float g_qkv  [(size_t)N_NODES*768];
__device__ float g_S    [(size_t)256*512*512];   // [B*H][512][512]
__device__ float g_attnO[(size_t)N_NODES*256];
__device__ float g_att  [(size_t)N_NODES*256];
__device__ float g_x2a  [(size_t)N_NODES*256];
__device__ float g_es   [N_NODES*4];
__device__ float g_ed   [N_NODES*4];
__device__ int   g_cnt   [N_NODES];
__device__ int   g_rowptr[N_NODES+1];
__device__ int   g_cursor[N_NODES];
__device__ int   g_col   [E_TOT];

// ---------------- warp reduce helpers ----------------
__device__ __forceinline__ float wsum(float v){
#pragma unroll
    for (int o=16;o;o>>=1) v += __shfl_xor_sync(0xffffffffu, v, o);
    return v;
}
__device__ __forceinline__ float wmax(float v){
#pragma unroll
    for (int o=16;o;o>>=1) v = fmaxf(v, __shfl_xor_sync(0xffffffffu, v, o));
    return v;
}

// ---------------- CSR build (edge_index is int32!) ----------------
__global__ void init_cnt_k(int* cnt){
    int i = blockIdx.x*blockDim.x + threadIdx.x;
    if (i < N_NODES) cnt[i] = 1;      // self-loop pre-counted
}
__global__ void hist_k(const int* __restrict__ ei, int* cnt){
    int e = blockIdx.x*blockDim.x + threadIdx.x;
    if (e < E_EDGES){
        int d = ei[E_EDGES + e];
        if (d >= 0 && d < N_NODES) atomicAdd(&cnt[d], 1);
    }
}
__global__ void scan_k(const int* __restrict__ cnt, int* rowptr, int* cursor){
    __shared__ int buf[1024];
    __shared__ int carry_s;
    int tid = threadIdx.x;
    if (tid == 0) carry_s = 0;
    __syncthreads();
    for (int base = 0; base < N_NODES; base += 1024){
        int v = cnt[base + tid];
        buf[tid] = v; __syncthreads();
        for (int off = 1; off < 1024; off <<= 1){
            int t = (tid >= off) ? buf[tid - off] : 0;
            __syncthreads();
            buf[tid] += t;
            __syncthreads();
        }
        int incl = buf[tid];
        int excl = incl - v + carry_s;
        rowptr[base + tid] = excl;
        cursor[base + tid] = excl;
        __syncthreads();
        if (tid == 1023) carry_s += incl;
        __syncthreads();
    }
    if (tid == 0) rowptr[N_NODES] = carry_s;
}
__global__ void scat_k(const int* __restrict__ ei, int* cursor, int* col){
    int e = blockIdx.x*blockDim.x + threadIdx.x;
    if (e < E_EDGES){
        int d = ei[E_EDGES + e];
        int s = ei[e];
        if (d >= 0 && d < N_NODES){
            int p = atomicAdd(&cursor[d], 1);
            col[p] = s;
        }
    }
}
__global__ void selfloop_k(int* cursor, int* col){
    int n = blockIdx.x*blockDim.x + threadIdx.x;
    if (n < N_NODES){
        int p = atomicAdd(&cursor[n], 1);
        col[p] = n;
    }
}

// ---------------- generic fp32 tile GEMM ----------------
// C[z] = alpha * A[z] @ op(B[z]) + bias ; offsets z1*s1 + z2*s2 with z1=z%ZD, z2=z/ZD
template<bool TRANSB>
__global__ __launch_bounds__(256) void gemm_k(
    const float* __restrict__ A, int lda, long long sA1, long long sA2,
    const float* __restrict__ B, int ldb, long long sB1, long long sB2,
    float* __restrict__ C, int ldc, long long sC1, long long sC2,
    const float* __restrict__ bias, int M, int Nn, int K, float alpha, int ZD)
{
    int z = blockIdx.z;
    long long z1 = z % ZD, z2 = z / ZD;
    A += z1*sA1 + z2*sA2;
    B += z1*sB1 + z2*sB2;
    C += z1*sC1 + z2*sC2;

    __shared__ float As[8][128];
    __shared__ float Bs[8][128];
    const int tid = threadIdx.x;
    const int m0 = blockIdx.y*128, n0 = blockIdx.x*128;
    const int ar  = tid >> 1, ac4 = (tid & 1)*4;
    const int ty  = tid >> 4, tx  = tid & 15;

    float acc[8][8];
#pragma unroll
    for (int i=0;i<8;i++)
#pragma unroll
        for (int j=0;j<8;j++) acc[i][j] = 0.f;

    for (int k0 = 0; k0 < K; k0 += 8){
        float4 av = *(const float4*)(A + (size_t)(m0+ar)*lda + k0 + ac4);
        As[ac4+0][ar]=av.x; As[ac4+1][ar]=av.y; As[ac4+2][ar]=av.z; As[ac4+3][ar]=av.w;
        if (!TRANSB){
            int bk = tid >> 5, bn4 = (tid & 31)*4;
            int n = n0 + bn4;
            float4 bv = make_float4(0.f,0.f,0.f,0.f);
            if (n < Nn) bv = *(const float4*)(B + (size_t)(k0+bk)*ldb + n);
            *(float4*)&Bs[bk][bn4] = bv;
        } else {
            int bn = tid >> 1, bk4 = (tid & 1)*4;
            int n = n0 + bn;
            float4 bv = make_float4(0.f,0.f,0.f,0.f);
            if (n < Nn) bv = *(const float4*)(B + (size_t)n*ldb + k0 + bk4);
            Bs[bk4+0][bn]=bv.x; Bs[bk4+1][bn]=bv.y; Bs[bk4+2][bn]=bv.z; Bs[bk4+3][bn]=bv.w;
        }
        __syncthreads();
#pragma unroll
        for (int kk=0;kk<8;kk++){
            float af[8], bf[8];
#pragma unroll
            for (int i=0;i<8;i++) af[i] = As[kk][ty*8+i];
#pragma unroll
            for (int j=0;j<8;j++) bf[j] = Bs[kk][tx*8+j];
#pragma unroll
            for (int i=0;i<8;i++)
#pragma unroll
                for (int j=0;j<8;j++) acc[i][j] += af[i]*bf[j];
        }
        __syncthreads();
    }
#pragma unroll
    for (int i=0;i<8;i++){
        int m = m0 + ty*8 + i;
#pragma unroll
        for (int j=0;j<8;j++){
            int n = n0 + tx*8 + j;
            if (n < Nn){
                float v = acc[i][j]*alpha;
                if (bias) v += bias[n];
                C[(size_t)m*ldc + n] = v;
            }
        }
    }
}

// ---------------- GAT score kernels ----------------
__global__ void scores4_k(const float* __restrict__ h, const float* __restrict__ aS,
                          const float* __restrict__ aD, float* __restrict__ es,
                          float* __restrict__ ed){
    int w = (blockIdx.x*blockDim.x + threadIdx.x) >> 5;
    int lane = threadIdx.x & 31;
    if (w >= N_NODES) return;
    const float* hr = h + (size_t)w*256;
#pragma unroll
    for (int hh=0; hh<4; hh++){
        float v0 = hr[hh*64+lane], v1 = hr[hh*64+32+lane];
        float ps = v0*aS[hh*64+lane] + v1*aS[hh*64+32+lane];
        float pd = v0*aD[hh*64+lane] + v1*aD[hh*64+32+lane];
        ps = wsum(ps); pd = wsum(pd);
        if (lane == 0){ es[w*4+hh] = ps; ed[w*4+hh] = pd; }
    }
}
__global__ void scores1_k(const float* __restrict__ h, const float* __restrict__ aS,
                          const float* __restrict__ aD, float* __restrict__ es,
                          float* __restrict__ ed){
    int w = (blockIdx.x*blockDim.x + threadIdx.x) >> 5;
    int lane = threadIdx.x & 31;
    if (w >= N_NODES) return;
    const float* hr = h + (size_t)w*128;
    float ps = 0.f, pd = 0.f;
#pragma unroll
    for (int i=0;i<4;i++){
        int ch = lane + i*32;
        ps += hr[ch]*aS[ch];
        pd += hr[ch]*aD[ch];
    }
    ps = wsum(ps); pd = wsum(pd);
    if (lane == 0){ es[w] = ps; ed[w] = pd; }
}

// ---------------- GAT aggregate (warp per dst node) ----------------
__global__ void agg4_k(const float* __restrict__ hbuf, const float* __restrict__ es,
                       const float* __restrict__ ed, const int* __restrict__ rowptr,
                       const int* __restrict__ col, const float* __restrict__ bias,
                       float* __restrict__ out, int do_elu){
    int w = (blockIdx.x*blockDim.x + threadIdx.x) >> 5;
    int lane = threadIdx.x & 31;
    if (w >= N_NODES) return;
    float edv[4];
#pragma unroll
    for (int h=0;h<4;h++) edv[h] = ed[w*4+h];
    int beg = rowptr[w], end = rowptr[w+1];

    float mx[4] = {-1e30f,-1e30f,-1e30f,-1e30f};
    for (int e = beg + lane; e < end; e += 32){
        int s = col[e];
#pragma unroll
        for (int h=0;h<4;h++){
            float v = es[s*4+h] + edv[h];
            v = (v >= 0.f) ? v : 0.2f*v;
            mx[h] = fmaxf(mx[h], v);
        }
    }
#pragma unroll
    for (int h=0;h<4;h++) mx[h] = wmax(mx[h]);

    float acc[8] = {0,0,0,0,0,0,0,0};
    float sh[4]  = {0,0,0,0};
    for (int e = beg; e < end; e++){
        int s = col[e];
        float pl = 0.f;
        if (lane < 4){
            float v = es[s*4+lane] + edv[lane];
            v = (v >= 0.f) ? v : 0.2f*v;
            pl = expf(v - mx[lane]);
        }
        float p[4];
#pragma unroll
        for (int h=0;h<4;h++) p[h] = __shfl_sync(0xffffffffu, pl, h);
#pragma unroll
        for (int h=0;h<4;h++) sh[h] += p[h];
        const float* hr = hbuf + (size_t)s*256;
#pragma unroll
        for (int i=0;i<8;i++){
            int ch = lane + i*32;
            acc[i] += p[i>>1] * hr[ch];
        }
    }
#pragma unroll
    for (int i=0;i<8;i++){
        int ch = lane + i*32;
        float v = acc[i]/sh[i>>1] + bias[ch];
        if (do_elu) v = (v > 0.f) ? v : expm1f(v);
        out[(size_t)w*256 + ch] = v;
    }
}
__global__ void agg1_k(const float* __restrict__ hbuf, const float* __restrict__ es,
                       const float* __restrict__ ed, const int* __restrict__ rowptr,
                       const int* __restrict__ col, const float* __restrict__ bias,
                       float* __restrict__ out){
    int w = (blockIdx.x*blockDim.x + threadIdx.x) >> 5;
    int lane = threadIdx.x & 31;
    if (w >= N_NODES) return;
    float edv = ed[w];
    int beg = rowptr[w], end = rowptr[w+1];

    float mx = -1e30f;
    for (int e = beg + lane; e < end; e += 32){
        float v = es[col[e]] + edv;
        v = (v >= 0.f) ? v : 0.2f*v;
        mx = fmaxf(mx, v);
    }
    mx = wmax(mx);

    float acc[4] = {0,0,0,0};
    float ssum = 0.f;
    for (int e = beg; e < end; e++){
        int s = col[e];
        float v = es[s] + edv;
        v = (v >= 0.f) ? v : 0.2f*v;
        float p = expf(v - mx);
        ssum += p;
        const float* hr = hbuf + (size_t)s*128;
#pragma unroll
        for (int i=0;i<4;i++){
            int ch = lane + i*32;
            acc[i] += p * hr[ch];
        }
    }
#pragma unroll
    for (int i=0;i<4;i++){
        int ch = lane + i*32;
        out[(size_t)w*128 + ch] = acc[i]/ssum + bias[ch];
    }
}

// ---------------- softmax rows (512 wide) ----------------
__global__ void softmax_k(float* __restrict__ S){
    int row = (blockIdx.x*blockDim.x + threadIdx.x) >> 5;
    int lane = threadIdx.x & 31;
    if (row >= 256*512) return;
    float* r = S + (size_t)row*512;
    float vals[16];
    float mx = -1e30f;
#pragma unroll
    for (int i=0;i<16;i++){ vals[i] = r[lane + i*32]; mx = fmaxf(mx, vals[i]); }
    mx = wmax(mx);
    float sum = 0.f;
#pragma unroll
    for (int i=0;i<16;i++){ vals[i] = expf(vals[i]-mx); sum += vals[i]; }
    sum = wsum(sum);
    float inv = 1.f/sum;
#pragma unroll
    for (int i=0;i<16;i++) r[lane + i*32] = vals[i]*inv;
}

// ---------------- residual + layernorm ----------------
__global__ void ln_k(const float* __restrict__ att, const float* __restrict__ x2,
                     const float* __restrict__ gamma, const float* __restrict__ beta,
                     float* __restrict__ out){
    int w = (blockIdx.x*blockDim.x + threadIdx.x) >> 5;
    int lane = threadIdx.x & 31;
    if (w >= N_NODES) return;
    float v[8];
    float s = 0.f;
#pragma unroll
    for (int i=0;i<8;i++){
        int ch = lane + i*32;
        v[i] = att[(size_t)w*256+ch] + x2[(size_t)w*256+ch];
        s += v[i];
    }
    s = wsum(s);
    float mean = s * (1.f/256.f);
    float sq = 0.f;
#pragma unroll
    for (int i=0;i<8;i++){ float d = v[i]-mean; sq += d*d; }
    sq = wsum(sq);
    float rstd = rsqrtf(sq*(1.f/256.f) + 1e-5f);
#pragma unroll
    for (int i=0;i<8;i++){
        int ch = lane + i*32;
        out[(size_t)w*256+ch] = (v[i]-mean)*rstd*gamma[ch] + beta[ch];
    }
}

// ---------------- host ----------------
static void launch_gemm(bool transb,
    const float* A,int lda,long long a1,long long a2,
    const float* B,int ldb,long long b1,long long b2,
    float* C,int ldc,long long c1,long long c2,
    const float* bias,int M,int Nn,int K,float alpha,int nz,int ZD)
{
    dim3 g((Nn+127)/128, (M+127)/128, nz);
    if (transb)
        gemm_k<true><<<g,256>>>(A,lda,a1,a2,B,ldb,b1,b2,C,ldc,c1,c2,bias,M,Nn,K,alpha,ZD);
    else
        gemm_k<false><<<g,256>>>(A,lda,a1,a2,B,ldb,b1,b2,C,ldc,c1,c2,bias,M,Nn,K,alpha,ZD);
}

extern "C" void kernel_launch(void* const* d_in, const int* in_sizes, int n_in,
                              void* d_out, int out_size)
{
    const float* x   = (const float*)d_in[0];
    const int*   ei  = (const int*)d_in[1];     // int32! (JAX default, no x64)
    const float* W1  = (const float*)d_in[3];
    const float* aS1 = (const float*)d_in[4];
    const float* aD1 = (const float*)d_in[5];
    const float* b1  = (const float*)d_in[6];
    const float* W2  = (const float*)d_in[7];
    const float* aS2 = (const float*)d_in[8];
    const float* aD2 = (const float*)d_in[9];
    const float* b2  = (const float*)d_in[10];
    const float* W3  = (const float*)d_in[11];
    const float* aS3 = (const float*)d_in[12];
    const float* aD3 = (const float*)d_in[13];
    const float* b3  = (const float*)d_in[14];
    const float* Wi  = (const float*)d_in[15];
    const float* bi  = (const float*)d_in[16];
    const float* Wo  = (const float*)d_in[17];
    const float* bo  = (const float*)d_in[18];
    const float* gam = (const float*)d_in[19];
    const float* bet = (const float*)d_in[20];
    float* out = (float*)d_out;

    float *h_, *x1_, *x2_, *qkv_, *S_, *attnO_, *att_, *x2a_, *es_, *ed_;
    int *cnt_, *rowptr_, *cursor_, *col_;
    cudaGetSymbolAddress((void**)&h_,     g_h);
    cudaGetSymbolAddress((void**)&x1_,    g_x1);
    cudaGetSymbolAddress((void**)&x2_,    g_x2);
    cudaGetSymbolAddress((void**)&qkv_,   g_qkv);
    cudaGetSymbolAddress((void**)&S_,     g_S);
    cudaGetSymbolAddress((void**)&attnO_, g_attnO);
    cudaGetSymbolAddress((void**)&att_,   g_att);
    cudaGetSymbolAddress((void**)&x2a_,   g_x2a);
    cudaGetSymbolAddress((void**)&es_,    g_es);
    cudaGetSymbolAddress((void**)&ed_,    g_ed);
    cudaGetSymbolAddress((void**)&cnt_,   g_cnt);
    cudaGetSymbolAddress((void**)&rowptr_,g_rowptr);
    cudaGetSymbolAddress((void**)&cursor_,g_cursor);
    cudaGetSymbolAddress((void**)&col_,   g_col);

    // ---- CSR by dst ----
    init_cnt_k<<<N_NODES/256,256>>>(cnt_);
    hist_k<<<E_EDGES/256,256>>>(ei, cnt_);
    scan_k<<<1,1024>>>(cnt_, rowptr_, cursor_);
    scat_k<<<E_EDGES/256,256>>>(ei, cursor_, col_);
    selfloop_k<<<N_NODES/256,256>>>(cursor_, col_);

    const int WBLK = 4096;  // warp-per-node kernels: 8 warps/block

    // ---- GAT layer 1 ----
    launch_gemm(false, x,128,0,0, W1,256,0,0, h_,256,0,0, nullptr, N_NODES,256,128, 1.f, 1,1);
    scores4_k<<<WBLK,256>>>(h_, aS1, aD1, es_, ed_);
    agg4_k<<<WBLK,256>>>(h_, es_, ed_, rowptr_, col_, b1, x1_, 1);

    // ---- GAT layer 2 ----
    launch_gemm(false, x1_,256,0,0, W2,256,0,0, h_,256,0,0, nullptr, N_NODES,256,256, 1.f, 1,1);
    scores4_k<<<WBLK,256>>>(h_, aS2, aD2, es_, ed_);
    agg4_k<<<WBLK,256>>>(h_, es_, ed_, rowptr_, col_, b2, x2_, 1);

    // ---- MHA ----
    launch_gemm(true,  x2_,256,0,0, Wi,256,0,0, qkv_,768,0,0, bi, N_NODES,768,256, 1.f, 1,1);
    // scores: per (b,h): Q[512,64] @ K^T -> S[512,512], scale 1/8
    launch_gemm(true,  qkv_,768, 64, 512LL*768, qkv_+256,768, 64, 512LL*768,
                S_,512, 262144LL, 1048576LL, nullptr, 512,512,64, 0.125f, 256,4);
    softmax_k<<<16384,256>>>(S_);
    // O = S @ V
    launch_gemm(false, S_,512, 262144LL, 1048576LL, qkv_+512,768, 64, 512LL*768,
                attnO_,256, 64LL, 512LL*256, nullptr, 512,64,512, 1.f, 256,4);
    // out proj
    launch_gemm(true,  attnO_,256,0,0, Wo,256,0,0, att_,256,0,0, bo, N_NODES,256,256, 1.f, 1,1);

    // ---- residual + LN ----
    ln_k<<<WBLK,256>>>(att_, x2_, gam, bet, x2a_);

    // ---- GAT layer 3 ----
    launch_gemm(false, x2a_,256,0,0, W3,128,0,0, h_,128,0,0, nullptr, N_NODES,128,256, 1.f, 1,1);
    scores1_k<<<WBLK,256>>>(h_, aS3, aD3, es_, ed_);
    agg1_k<<<WBLK,256>>>(h_, es_, ed_, rowptr_, col_, b3, out);
}

// round 3
// speedup vs baseline: 1.9724x; 1.9724x over previous
#include <cuda_runtime.h>
#include <math.h>

#define N_NODES 32768
#define E_EDGES 524288
#define E_TOT   (E_EDGES + N_NODES)

// ---------------- scratch (device globals; no runtime allocation) ----------------
__device__ float g_h    [(size_t)N_NODES*256];
__device__ float g_x1   [(size_t)N_NODES*256];
__device__ float g_x2   [(size_t)N_NODES*256];
__device__ float g_qkv  [(size_t)N_NODES*768];
__device__ float g_S    [(size_t)256*512*512];   // [B*H][512][512]
__device__ float g_attnO[(size_t)N_NODES*256];
__device__ float g_att  [(size_t)N_NODES*256];
__device__ float g_x2a  [(size_t)N_NODES*256];
__device__ float g_es   [N_NODES*4];
__device__ float g_ed   [N_NODES*4];
__device__ int   g_cnt   [N_NODES];
__device__ int   g_rowptr[N_NODES+1];
__device__ int   g_cursor[N_NODES];
__device__ int   g_col   [E_TOT];

// ---------------- warp reduce helpers ----------------
__device__ __forceinline__ float wsum(float v){
#pragma unroll
    for (int o=16;o;o>>=1) v += __shfl_xor_sync(0xffffffffu, v, o);
    return v;
}
__device__ __forceinline__ float wmax(float v){
#pragma unroll
    for (int o=16;o;o>>=1) v = fmaxf(v, __shfl_xor_sync(0xffffffffu, v, o));
    return v;
}

// ---------------- CSR build (edge_index is int32) ----------------
__global__ void init_cnt_k(int* cnt){
    int i = blockIdx.x*blockDim.x + threadIdx.x;
    if (i < N_NODES) cnt[i] = 1;      // self-loop pre-counted
}
__global__ void hist_k(const int* __restrict__ ei, int* cnt){
    int e = blockIdx.x*blockDim.x + threadIdx.x;
    if (e < E_EDGES){
        int d = ei[E_EDGES + e];
        if (d >= 0 && d < N_NODES) atomicAdd(&cnt[d], 1);
    }
}
__global__ void scan_k(const int* __restrict__ cnt, int* rowptr, int* cursor){
    __shared__ int buf[1024];
    __shared__ int carry_s;
    int tid = threadIdx.x;
    if (tid == 0) carry_s = 0;
    __syncthreads();
    for (int base = 0; base < N_NODES; base += 1024){
        int v = cnt[base + tid];
        buf[tid] = v; __syncthreads();
        for (int off = 1; off < 1024; off <<= 1){
            int t = (tid >= off) ? buf[tid - off] : 0;
            __syncthreads();
            buf[tid] += t;
            __syncthreads();
        }
        int incl = buf[tid];
        int excl = incl - v + carry_s;
        rowptr[base + tid] = excl;
        cursor[base + tid] = excl;
        __syncthreads();
        if (tid == 1023) carry_s += incl;
        __syncthreads();
    }
    if (tid == 0) rowptr[N_NODES] = carry_s;
}
__global__ void scat_k(const int* __restrict__ ei, int* cursor, int* col){
    int e = blockIdx.x*blockDim.x + threadIdx.x;
    if (e < E_EDGES){
        int d = ei[E_EDGES + e];
        int s = ei[e];
        if (d >= 0 && d < N_NODES){
            int p = atomicAdd(&cursor[d], 1);
            col[p] = s;
        }
    }
}
__global__ void selfloop_k(int* cursor, int* col){
    int n = blockIdx.x*blockDim.x + threadIdx.x;
    if (n < N_NODES){
        int p = atomicAdd(&cursor[n], 1);
        col[p] = n;
    }
}

// ---------------- tf32 tensor-core GEMM ----------------
// C[z] = alpha * A[z] @ op(B[z]) + bias
// A row-major [M,K]; B [K,N] (or [N,K] if TRANSB). M % 128 == 0, K % 16 == 0,
// Nn % 8 == 0 (float4 path needs Nn % 4 == 0; all our Nn are multiples of 64).
__device__ __forceinline__ unsigned f2tf(float f){
    unsigned u; asm("cvt.rna.tf32.f32 %0, %1;" : "=r"(u) : "f"(f)); return u;
}

template<bool TRANSB>
__global__ __launch_bounds__(256) void gemm_tc(
    const float* __restrict__ A, int lda, long long sA1, long long sA2,
    const float* __restrict__ B, int ldb, long long sB1, long long sB2,
    float* __restrict__ C, int ldc, long long sC1, long long sC2,
    const float* __restrict__ bias, int Nn, int K, float alpha, int ZD)
{
    int z = blockIdx.z;
    long long z1 = z % ZD, z2 = z / ZD;
    A += z1*sA1 + z2*sA2;
    B += z1*sB1 + z2*sB2;
    C += z1*sC1 + z2*sC2;

    __shared__ unsigned As[16][136];   // [k][m], pad 136 -> conflict-free frag loads
    __shared__ unsigned Bs[16][136];   // [k][n]

    const int tid  = threadIdx.x;
    const int lane = tid & 31, warp = tid >> 5;
    const int m0 = blockIdx.y*128, n0 = blockIdx.x*128;
    const int wm = (warp & 1)*64, wn = (warp >> 1)*32;
    const int r = lane >> 2, cq = lane & 3;

    float acc[4][4][4];
#pragma unroll
    for (int a=0;a<4;a++)
#pragma unroll
    for (int b=0;b<4;b++)
#pragma unroll
    for (int c=0;c<4;c++) acc[a][b][c] = 0.f;

    for (int k0 = 0; k0 < K; k0 += 16){
        // stage A (transpose to k-major, cvt to tf32)
#pragma unroll
        for (int l=0;l<2;l++){
            int fid = tid + l*256;
            int m = fid >> 2, c4 = (fid & 3)*4;
            float4 v = *(const float4*)(A + (size_t)(m0+m)*lda + k0 + c4);
            As[c4+0][m]=f2tf(v.x); As[c4+1][m]=f2tf(v.y);
            As[c4+2][m]=f2tf(v.z); As[c4+3][m]=f2tf(v.w);
        }
        if (!TRANSB){
#pragma unroll
            for (int l=0;l<2;l++){
                int fid = tid + l*256;
                int k = fid >> 5, n4 = (fid & 31)*4;
                float4 v = make_float4(0.f,0.f,0.f,0.f);
                if (n0+n4 < Nn) v = *(const float4*)(B + (size_t)(k0+k)*ldb + n0 + n4);
                Bs[k][n4+0]=f2tf(v.x); Bs[k][n4+1]=f2tf(v.y);
                Bs[k][n4+2]=f2tf(v.z); Bs[k][n4+3]=f2tf(v.w);
            }
        } else {
#pragma unroll
            for (int l=0;l<2;l++){
                int fid = tid + l*256;
                int n = fid >> 2, k4 = (fid & 3)*4;
                float4 v = make_float4(0.f,0.f,0.f,0.f);
                if (n0+n < Nn) v = *(const float4*)(B + (size_t)(n0+n)*ldb + k0 + k4);
                Bs[k4+0][n]=f2tf(v.x); Bs[k4+1][n]=f2tf(v.y);
                Bs[k4+2][n]=f2tf(v.z); Bs[k4+3][n]=f2tf(v.w);
            }
        }
        __syncthreads();
#pragma unroll
        for (int ks=0; ks<2; ks++){
            const int kb = ks*8;
            unsigned af[4][4], bf[4][2];
#pragma unroll
            for (int mt=0;mt<4;mt++){
                int mb = wm + mt*16;
                af[mt][0] = As[kb+cq  ][mb+r];
                af[mt][1] = As[kb+cq  ][mb+r+8];
                af[mt][2] = As[kb+cq+4][mb+r];
                af[mt][3] = As[kb+cq+4][mb+r+8];
            }
#pragma unroll
            for (int nt=0;nt<4;nt++){
                int nb = wn + nt*8;
                bf[nt][0] = Bs[kb+cq  ][nb+r];
                bf[nt][1] = Bs[kb+cq+4][nb+r];
            }
#pragma unroll
            for (int mt=0;mt<4;mt++)
#pragma unroll
            for (int nt=0;nt<4;nt++){
                asm volatile(
                  "mma.sync.aligned.m16n8k8.row.col.f32.tf32.tf32.f32 "
                  "{%0,%1,%2,%3}, {%4,%5,%6,%7}, {%8,%9}, {%0,%1,%2,%3};\n"
                  : "+f"(acc[mt][nt][0]), "+f"(acc[mt][nt][1]),
                    "+f"(acc[mt][nt][2]), "+f"(acc[mt][nt][3])
                  : "r"(af[mt][0]),"r"(af[mt][1]),"r"(af[mt][2]),"r"(af[mt][3]),
                    "r"(bf[nt][0]),"r"(bf[nt][1]));
            }
        }
        __syncthreads();
    }

    // epilogue (c0,c1: row=group, cols 2q,2q+1 ; c2,c3: row=group+8)
#pragma unroll
    for (int mt=0;mt<4;mt++){
        int row0 = m0 + wm + mt*16 + r;
#pragma unroll
        for (int nt=0;nt<4;nt++){
            int col = n0 + wn + nt*8 + 2*cq;
            if (col < Nn){
                float bv0 = bias ? bias[col]   : 0.f;
                float bv1 = bias ? bias[col+1] : 0.f;
                C[(size_t)row0*ldc + col]       = acc[mt][nt][0]*alpha + bv0;
                C[(size_t)row0*ldc + col + 1]   = acc[mt][nt][1]*alpha + bv1;
                C[(size_t)(row0+8)*ldc + col]   = acc[mt][nt][2]*alpha + bv0;
                C[(size_t)(row0+8)*ldc + col+1] = acc[mt][nt][3]*alpha + bv1;
            }
        }
    }
}

// ---------------- GAT score kernels ----------------
__global__ void scores4_k(const float* __restrict__ h, const float* __restrict__ aS,
                          const float* __restrict__ aD, float* __restrict__ es,
                          float* __restrict__ ed){
    int w = (blockIdx.x*blockDim.x + threadIdx.x) >> 5;
    int lane = threadIdx.x & 31;
    if (w >= N_NODES) return;
    const float* hr = h + (size_t)w*256;
#pragma unroll
    for (int hh=0; hh<4; hh++){
        float v0 = hr[hh*64+lane], v1 = hr[hh*64+32+lane];
        float ps = v0*aS[hh*64+lane] + v1*aS[hh*64+32+lane];
        float pd = v0*aD[hh*64+lane] + v1*aD[hh*64+32+lane];
        ps = wsum(ps); pd = wsum(pd);
        if (lane == 0){ es[w*4+hh] = ps; ed[w*4+hh] = pd; }
    }
}
__global__ void scores1_k(const float* __restrict__ h, const float* __restrict__ aS,
                          const float* __restrict__ aD, float* __restrict__ es,
                          float* __restrict__ ed){
    int w = (blockIdx.x*blockDim.x + threadIdx.x) >> 5;
    int lane = threadIdx.x & 31;
    if (w >= N_NODES) return;
    const float* hr = h + (size_t)w*128;
    float ps = 0.f, pd = 0.f;
#pragma unroll
    for (int i=0;i<4;i++){
        int ch = lane + i*32;
        ps += hr[ch]*aS[ch];
        pd += hr[ch]*aD[ch];
    }
    ps = wsum(ps); pd = wsum(pd);
    if (lane == 0){ es[w] = ps; ed[w] = pd; }
}

// ---------------- GAT aggregate (warp per dst node) ----------------
__global__ void agg4_k(const float* __restrict__ hbuf, const float* __restrict__ es,
                       const float* __restrict__ ed, const int* __restrict__ rowptr,
                       const int* __restrict__ col, const float* __restrict__ bias,
                       float* __restrict__ out, int do_elu){
    int w = (blockIdx.x*blockDim.x + threadIdx.x) >> 5;
    int lane = threadIdx.x & 31;
    if (w >= N_NODES) return;
    float edv[4];
#pragma unroll
    for (int h=0;h<4;h++) edv[h] = ed[w*4+h];
    int beg = rowptr[w], end = rowptr[w+1];

    float mx[4] = {-1e30f,-1e30f,-1e30f,-1e30f};
    for (int e = beg + lane; e < end; e += 32){
        int s = col[e];
#pragma unroll
        for (int h=0;h<4;h++){
            float v = es[s*4+h] + edv[h];
            v = (v >= 0.f) ? v : 0.2f*v;
            mx[h] = fmaxf(mx[h], v);
        }
    }
#pragma unroll
    for (int h=0;h<4;h++) mx[h] = wmax(mx[h]);

    float acc[8] = {0,0,0,0,0,0,0,0};
    float sh[4]  = {0,0,0,0};
    for (int e = beg; e < end; e++){
        int s = col[e];
        float pl = 0.f;
        if (lane < 4){
            float v = es[s*4+lane] + edv[lane];
            v = (v >= 0.f) ? v : 0.2f*v;
            pl = expf(v - mx[lane]);
        }
        float p[4];
#pragma unroll
        for (int h=0;h<4;h++) p[h] = __shfl_sync(0xffffffffu, pl, h);
#pragma unroll
        for (int h=0;h<4;h++) sh[h] += p[h];
        const float* hr = hbuf + (size_t)s*256;
#pragma unroll
        for (int i=0;i<8;i++){
            int ch = lane + i*32;
            acc[i] += p[i>>1] * hr[ch];
        }
    }
#pragma unroll
    for (int i=0;i<8;i++){
        int ch = lane + i*32;
        float v = acc[i]/sh[i>>1] + bias[ch];
        if (do_elu) v = (v > 0.f) ? v : expm1f(v);
        out[(size_t)w*256 + ch] = v;
    }
}
__global__ void agg1_k(const float* __restrict__ hbuf, const float* __restrict__ es,
                       const float* __restrict__ ed, const int* __restrict__ rowptr,
                       const int* __restrict__ col, const float* __restrict__ bias,
                       float* __restrict__ out){
    int w = (blockIdx.x*blockDim.x + threadIdx.x) >> 5;
    int lane = threadIdx.x & 31;
    if (w >= N_NODES) return;
    float edv = ed[w];
    int beg = rowptr[w], end = rowptr[w+1];

    float mx = -1e30f;
    for (int e = beg + lane; e < end; e += 32){
        float v = es[col[e]] + edv;
        v = (v >= 0.f) ? v : 0.2f*v;
        mx = fmaxf(mx, v);
    }
    mx = wmax(mx);

    float acc[4] = {0,0,0,0};
    float ssum = 0.f;
    for (int e = beg; e < end; e++){
        int s = col[e];
        float v = es[s] + edv;
        v = (v >= 0.f) ? v : 0.2f*v;
        float p = expf(v - mx);
        ssum += p;
        const float* hr = hbuf + (size_t)s*128;
#pragma unroll
        for (int i=0;i<4;i++){
            int ch = lane + i*32;
            acc[i] += p * hr[ch];
        }
    }
#pragma unroll
    for (int i=0;i<4;i++){
        int ch = lane + i*32;
        out[(size_t)w*128 + ch] = acc[i]/ssum + bias[ch];
    }
}

// ---------------- softmax rows (512 wide) ----------------
__global__ void softmax_k(float* __restrict__ S){
    int row = (blockIdx.x*blockDim.x + threadIdx.x) >> 5;
    int lane = threadIdx.x & 31;
    if (row >= 256*512) return;
    float* r = S + (size_t)row*512;
    float vals[16];
    float mx = -1e30f;
#pragma unroll
    for (int i=0;i<16;i++){ vals[i] = r[lane + i*32]; mx = fmaxf(mx, vals[i]); }
    mx = wmax(mx);
    float sum = 0.f;
#pragma unroll
    for (int i=0;i<16;i++){ vals[i] = expf(vals[i]-mx); sum += vals[i]; }
    sum = wsum(sum);
    float inv = 1.f/sum;
#pragma unroll
    for (int i=0;i<16;i++) r[lane + i*32] = vals[i]*inv;
}

// ---------------- residual + layernorm ----------------
__global__ void ln_k(const float* __restrict__ att, const float* __restrict__ x2,
                     const float* __restrict__ gamma, const float* __restrict__ beta,
                     float* __restrict__ out){
    int w = (blockIdx.x*blockDim.x + threadIdx.x) >> 5;
    int lane = threadIdx.x & 31;
    if (w >= N_NODES) return;
    float v[8];
    float s = 0.f;
#pragma unroll
    for (int i=0;i<8;i++){
        int ch = lane + i*32;
        v[i] = att[(size_t)w*256+ch] + x2[(size_t)w*256+ch];
        s += v[i];
    }
    s = wsum(s);
    float mean = s * (1.f/256.f);
    float sq = 0.f;
#pragma unroll
    for (int i=0;i<8;i++){ float d = v[i]-mean; sq += d*d; }
    sq = wsum(sq);
    float rstd = rsqrtf(sq*(1.f/256.f) + 1e-5f);
#pragma unroll
    for (int i=0;i<8;i++){
        int ch = lane + i*32;
        out[(size_t)w*256+ch] = (v[i]-mean)*rstd*gamma[ch] + beta[ch];
    }
}

// ---------------- host ----------------
static void launch_gemm(bool transb,
    const float* A,int lda,long long a1,long long a2,
    const float* B,int ldb,long long b1,long long b2,
    float* C,int ldc,long long c1,long long c2,
    const float* bias,int M,int Nn,int K,float alpha,int nz,int ZD)
{
    dim3 g((Nn+127)/128, (M+127)/128, nz);
    if (transb)
        gemm_tc<true><<<g,256>>>(A,lda,a1,a2,B,ldb,b1,b2,C,ldc,c1,c2,bias,Nn,K,alpha,ZD);
    else
        gemm_tc<false><<<g,256>>>(A,lda,a1,a2,B,ldb,b1,b2,C,ldc,c1,c2,bias,Nn,K,alpha,ZD);
}

extern "C" void kernel_launch(void* const* d_in, const int* in_sizes, int n_in,
                              void* d_out, int out_size)
{
    const float* x   = (const float*)d_in[0];
    const int*   ei  = (const int*)d_in[1];     // int32 (JAX default, no x64)
    const float* W1  = (const float*)d_in[3];
    const float* aS1 = (const float*)d_in[4];
    const float* aD1 = (const float*)d_in[5];
    const float* b1  = (const float*)d_in[6];
    const float* W2  = (const float*)d_in[7];
    const float* aS2 = (const float*)d_in[8];
    const float* aD2 = (const float*)d_in[9];
    const float* b2  = (const float*)d_in[10];
    const float* W3  = (const float*)d_in[11];
    const float* aS3 = (const float*)d_in[12];
    const float* aD3 = (const float*)d_in[13];
    const float* b3  = (const float*)d_in[14];
    const float* Wi  = (const float*)d_in[15];
    const float* bi  = (const float*)d_in[16];
    const float* Wo  = (const float*)d_in[17];
    const float* bo  = (const float*)d_in[18];
    const float* gam = (const float*)d_in[19];
    const float* bet = (const float*)d_in[20];
    float* out = (float*)d_out;

    float *h_, *x1_, *x2_, *qkv_, *S_, *attnO_, *att_, *x2a_, *es_, *ed_;
    int *cnt_, *rowptr_, *cursor_, *col_;
    cudaGetSymbolAddress((void**)&h_,     g_h);
    cudaGetSymbolAddress((void**)&x1_,    g_x1);
    cudaGetSymbolAddress((void**)&x2_,    g_x2);
    cudaGetSymbolAddress((void**)&qkv_,   g_qkv);
    cudaGetSymbolAddress((void**)&S_,     g_S);
    cudaGetSymbolAddress((void**)&attnO_, g_attnO);
    cudaGetSymbolAddress((void**)&att_,   g_att);
    cudaGetSymbolAddress((void**)&x2a_,   g_x2a);
    cudaGetSymbolAddress((void**)&es_,    g_es);
    cudaGetSymbolAddress((void**)&ed_,    g_ed);
    cudaGetSymbolAddress((void**)&cnt_,   g_cnt);
    cudaGetSymbolAddress((void**)&rowptr_,g_rowptr);
    cudaGetSymbolAddress((void**)&cursor_,g_cursor);
    cudaGetSymbolAddress((void**)&col_,   g_col);

    // ---- CSR by dst ----
    init_cnt_k<<<N_NODES/256,256>>>(cnt_);
    hist_k<<<E_EDGES/256,256>>>(ei, cnt_);
    scan_k<<<1,1024>>>(cnt_, rowptr_, cursor_);
    scat_k<<<E_EDGES/256,256>>>(ei, cursor_, col_);
    selfloop_k<<<N_NODES/256,256>>>(cursor_, col_);

    const int WBLK = 4096;  // warp-per-node kernels: 8 warps/block

    // ---- GAT layer 1 ----
    launch_gemm(false, x,128,0,0, W1,256,0,0, h_,256,0,0, nullptr, N_NODES,256,128, 1.f, 1,1);
    scores4_k<<<WBLK,256>>>(h_, aS1, aD1, es_, ed_);
    agg4_k<<<WBLK,256>>>(h_, es_, ed_, rowptr_, col_, b1, x1_, 1);

    // ---- GAT layer 2 ----
    launch_gemm(false, x1_,256,0,0, W2,256,0,0, h_,256,0,0, nullptr, N_NODES,256,256, 1.f, 1,1);
    scores4_k<<<WBLK,256>>>(h_, aS2, aD2, es_, ed_);
    agg4_k<<<WBLK,256>>>(h_, es_, ed_, rowptr_, col_, b2, x2_, 1);

    // ---- MHA ----
    launch_gemm(true,  x2_,256,0,0, Wi,256,0,0, qkv_,768,0,0, bi, N_NODES,768,256, 1.f, 1,1);
    // scores: per (b,h): Q[512,64] @ K^T -> S[512,512], scale 1/8
    launch_gemm(true,  qkv_,768, 64, 512LL*768, qkv_+256,768, 64, 512LL*768,
                S_,512, 262144LL, 1048576LL, nullptr, 512,512,64, 0.125f, 256,4);
    softmax_k<<<16384,256>>>(S_);
    // O = S @ V
    launch_gemm(false, S_,512, 262144LL, 1048576LL, qkv_+512,768, 64, 512LL*768,
                attnO_,256, 64LL, 512LL*256, nullptr, 512,64,512, 1.f, 256,4);
    // out proj
    launch_gemm(true,  attnO_,256,0,0, Wo,256,0,0, att_,256,0,0, bo, N_NODES,256,256, 1.f, 1,1);

    // ---- residual + LN ----
    ln_k<<<WBLK,256>>>(att_, x2_, gam, bet, x2a_);

    // ---- GAT layer 3 ----
    launch_gemm(false, x2a_,256,0,0, W3,128,0,0, h_,128,0,0, nullptr, N_NODES,128,256, 1.f, 1,1);
    scores1_k<<<WBLK,256>>>(h_, aS3, aD3, es_, ed_);
    agg1_k<<<WBLK,256>>>(h_, es_, ed_, rowptr_, col_, b3, out);
}

// round 4
// speedup vs baseline: 2.4072x; 1.2204x over previous
#include <cuda_runtime.h>
#include <math.h>

#define N_NODES 32768
#define E_EDGES 524288
#define E_TOT   (E_EDGES + N_NODES)

// ---------------- scratch (device globals; no runtime allocation) ----------------
__device__ float g_h    [(size_t)N_NODES*256];
__device__ float g_x1   [(size_t)N_NODES*256];
__device__ float g_x2   [(size_t)N_NODES*256];
__device__ float g_qkv  [(size_t)N_NODES*768];
__device__ float g_attnO[(size_t)N_NODES*256];
__device__ float g_att  [(size_t)N_NODES*256];
__device__ float g_x2a  [(size_t)N_NODES*256];
__device__ float g_es   [N_NODES*4];
__device__ float g_ed   [N_NODES*4];
__device__ int   g_cnt   [N_NODES];
__device__ int   g_rowptr[N_NODES+1];
__device__ int   g_cursor[N_NODES];
__device__ int   g_col   [E_TOT];

// ---------------- warp reduce helpers ----------------
__device__ __forceinline__ float wsum(float v){
#pragma unroll
    for (int o=16;o;o>>=1) v += __shfl_xor_sync(0xffffffffu, v, o);
    return v;
}
__device__ __forceinline__ float wmax(float v){
#pragma unroll
    for (int o=16;o;o>>=1) v = fmaxf(v, __shfl_xor_sync(0xffffffffu, v, o));
    return v;
}

// ---------------- CSR build (edge_index is int32) ----------------
__global__ void init_cnt_k(int* cnt){
    int i = blockIdx.x*blockDim.x + threadIdx.x;
    if (i < N_NODES) cnt[i] = 1;      // self-loop pre-counted
}
__global__ void hist_k(const int* __restrict__ ei, int* cnt){
    int e = blockIdx.x*blockDim.x + threadIdx.x;
    if (e < E_EDGES){
        int d = ei[E_EDGES + e];
        if (d >= 0 && d < N_NODES) atomicAdd(&cnt[d], 1);
    }
}
__global__ void scan_k(const int* __restrict__ cnt, int* rowptr, int* cursor){
    __shared__ int buf[1024];
    __shared__ int carry_s;
    int tid = threadIdx.x;
    if (tid == 0) carry_s = 0;
    __syncthreads();
    for (int base = 0; base < N_NODES; base += 1024){
        int v = cnt[base + tid];
        buf[tid] = v; __syncthreads();
        for (int off = 1; off < 1024; off <<= 1){
            int t = (tid >= off) ? buf[tid - off] : 0;
            __syncthreads();
            buf[tid] += t;
            __syncthreads();
        }
        int incl = buf[tid];
        int excl = incl - v + carry_s;
        rowptr[base + tid] = excl;
        cursor[base + tid] = excl;
        __syncthreads();
        if (tid == 1023) carry_s += incl;
        __syncthreads();
    }
    if (tid == 0) rowptr[N_NODES] = carry_s;
}
__global__ void scat_k(const int* __restrict__ ei, int* cursor, int* col){
    int e = blockIdx.x*blockDim.x + threadIdx.x;
    if (e < E_EDGES){
        int d = ei[E_EDGES + e];
        int s = ei[e];
        if (d >= 0 && d < N_NODES){
            int p = atomicAdd(&cursor[d], 1);
            col[p] = s;
        }
    }
}
__global__ void selfloop_k(int* cursor, int* col){
    int n = blockIdx.x*blockDim.x + threadIdx.x;
    if (n < N_NODES){
        int p = atomicAdd(&cursor[n], 1);
        col[p] = n;
    }
}

// ---------------- tf32 helpers ----------------
__device__ __forceinline__ unsigned f2tf(float f){
    unsigned u; asm("cvt.rna.tf32.f32 %0, %1;" : "=r"(u) : "f"(f)); return u;
}
__device__ __forceinline__ void mma_tf32(float* c, const unsigned* a, unsigned b0, unsigned b1){
    asm volatile(
      "mma.sync.aligned.m16n8k8.row.col.f32.tf32.tf32.f32 "
      "{%0,%1,%2,%3}, {%4,%5,%6,%7}, {%8,%9}, {%0,%1,%2,%3};\n"
      : "+f"(c[0]), "+f"(c[1]), "+f"(c[2]), "+f"(c[3])
      : "r"(a[0]),"r"(a[1]),"r"(a[2]),"r"(a[3]), "r"(b0),"r"(b1));
}

// ---------------- tf32 tensor-core GEMM ----------------
template<bool TRANSB>
__global__ __launch_bounds__(256) void gemm_tc(
    const float* __restrict__ A, int lda, long long sA1, long long sA2,
    const float* __restrict__ B, int ldb, long long sB1, long long sB2,
    float* __restrict__ C, int ldc, long long sC1, long long sC2,
    const float* __restrict__ bias, int Nn, int K, float alpha, int ZD)
{
    int z = blockIdx.z;
    long long z1 = z % ZD, z2 = z / ZD;
    A += z1*sA1 + z2*sA2;
    B += z1*sB1 + z2*sB2;
    C += z1*sC1 + z2*sC2;

    __shared__ unsigned As[16][136];
    __shared__ unsigned Bs[16][136];

    const int tid  = threadIdx.x;
    const int lane = tid & 31, warp = tid >> 5;
    const int m0 = blockIdx.y*128, n0 = blockIdx.x*128;
    const int wm = (warp & 1)*64, wn = (warp >> 1)*32;
    const int r = lane >> 2, cq = lane & 3;

    float acc[4][4][4];
#pragma unroll
    for (int a=0;a<4;a++)
#pragma unroll
    for (int b=0;b<4;b++)
#pragma unroll
    for (int c=0;c<4;c++) acc[a][b][c] = 0.f;

    for (int k0 = 0; k0 < K; k0 += 16){
#pragma unroll
        for (int l=0;l<2;l++){
            int fid = tid + l*256;
            int m = fid >> 2, c4 = (fid & 3)*4;
            float4 v = *(const float4*)(A + (size_t)(m0+m)*lda + k0 + c4);
            As[c4+0][m]=f2tf(v.x); As[c4+1][m]=f2tf(v.y);
            As[c4+2][m]=f2tf(v.z); As[c4+3][m]=f2tf(v.w);
        }
        if (!TRANSB){
#pragma unroll
            for (int l=0;l<2;l++){
                int fid = tid + l*256;
                int k = fid >> 5, n4 = (fid & 31)*4;
                float4 v = make_float4(0.f,0.f,0.f,0.f);
                if (n0+n4 < Nn) v = *(const float4*)(B + (size_t)(k0+k)*ldb + n0 + n4);
                Bs[k][n4+0]=f2tf(v.x); Bs[k][n4+1]=f2tf(v.y);
                Bs[k][n4+2]=f2tf(v.z); Bs[k][n4+3]=f2tf(v.w);
            }
        } else {
#pragma unroll
            for (int l=0;l<2;l++){
                int fid = tid + l*256;
                int n = fid >> 2, k4 = (fid & 3)*4;
                float4 v = make_float4(0.f,0.f,0.f,0.f);
                if (n0+n < Nn) v = *(const float4*)(B + (size_t)(n0+n)*ldb + k0 + k4);
                Bs[k4+0][n]=f2tf(v.x); Bs[k4+1][n]=f2tf(v.y);
                Bs[k4+2][n]=f2tf(v.z); Bs[k4+3][n]=f2tf(v.w);
            }
        }
        __syncthreads();
#pragma unroll
        for (int ks=0; ks<2; ks++){
            const int kb = ks*8;
            unsigned af[4][4], bf[4][2];
#pragma unroll
            for (int mt=0;mt<4;mt++){
                int mb = wm + mt*16;
                af[mt][0] = As[kb+cq  ][mb+r];
                af[mt][1] = As[kb+cq  ][mb+r+8];
                af[mt][2] = As[kb+cq+4][mb+r];
                af[mt][3] = As[kb+cq+4][mb+r+8];
            }
#pragma unroll
            for (int nt=0;nt<4;nt++){
                int nb = wn + nt*8;
                bf[nt][0] = Bs[kb+cq  ][nb+r];
                bf[nt][1] = Bs[kb+cq+4][nb+r];
            }
#pragma unroll
            for (int mt=0;mt<4;mt++)
#pragma unroll
            for (int nt=0;nt<4;nt++)
                mma_tf32(acc[mt][nt], af[mt], bf[nt][0], bf[nt][1]);
        }
        __syncthreads();
    }

#pragma unroll
    for (int mt=0;mt<4;mt++){
        int row0 = m0 + wm + mt*16 + r;
#pragma unroll
        for (int nt=0;nt<4;nt++){
            int col = n0 + wn + nt*8 + 2*cq;
            if (col < Nn){
                float bv0 = bias ? bias[col]   : 0.f;
                float bv1 = bias ? bias[col+1] : 0.f;
                C[(size_t)row0*ldc + col]       = acc[mt][nt][0]*alpha + bv0;
                C[(size_t)row0*ldc + col + 1]   = acc[mt][nt][1]*alpha + bv1;
                C[(size_t)(row0+8)*ldc + col]   = acc[mt][nt][2]*alpha + bv0;
                C[(size_t)(row0+8)*ldc + col+1] = acc[mt][nt][3]*alpha + bv1;
            }
        }
    }
}

// ---------------- fused flash attention ----------------
// qkv: [N, 768] rows (Q|K|V per head group of 64). grid: (4 q-tiles, 256 bh).
// Block = 256 threads, warp w owns q rows [w*16, w*16+16).
#define KS_STRIDE 68
#define VS_STRIDE 72
#define PS_STRIDE 68
#define FLASH_SMEM ((64*KS_STRIDE + 64*VS_STRIDE + 8*16*PS_STRIDE)*4)

__global__ __launch_bounds__(256,1) void flash_k(const float* __restrict__ qkv,
                                                 float* __restrict__ o)
{
    extern __shared__ unsigned sm[];
    unsigned* Ks = sm;                       // [key 64][feat 64] stride 68
    unsigned* Vs = Ks + 64*KS_STRIDE;        // [key 64][d 64]    stride 72
    unsigned* Ps = Vs + 64*VS_STRIDE;        // [warp 8][row 16][col 64] stride 68

    const int qt = blockIdx.x, bh = blockIdx.y;
    const int b = bh >> 2, h = bh & 3;
    const int tid = threadIdx.x, w = tid >> 5, lane = tid & 31;
    const int r = lane >> 2, cq = lane & 3;
    const int q0 = qt*128;
    unsigned* Psb = Ps + w*16*PS_STRIDE;

    // Q fragments in registers (pre-scaled by 1/sqrt(64)=0.125; exact pow2)
    const float* Q = qkv + (size_t)(b*512 + q0 + w*16)*768 + h*64;
    unsigned qf[8][4];
#pragma unroll
    for (int kt=0;kt<8;kt++){
        int c0 = kt*8 + cq;
        qf[kt][0] = f2tf(0.125f * Q[(size_t)r*768     + c0]);
        qf[kt][1] = f2tf(0.125f * Q[(size_t)(r+8)*768 + c0]);
        qf[kt][2] = f2tf(0.125f * Q[(size_t)r*768     + c0+4]);
        qf[kt][3] = f2tf(0.125f * Q[(size_t)(r+8)*768 + c0+4]);
    }

    float oacc[8][4];
#pragma unroll
    for (int dt=0;dt<8;dt++)
#pragma unroll
    for (int i=0;i<4;i++) oacc[dt][i] = 0.f;
    float m_lo=-1e30f, m_hi=-1e30f, l_lo=0.f, l_hi=0.f;

    for (int c=0;c<8;c++){
        __syncthreads();
        // stage K,V chunk [64 keys][64 feats]
        {
            int row = tid >> 2, f0 = (tid & 3)*16;
            const float* Kr = qkv + (size_t)(b*512 + c*64 + row)*768 + 256 + h*64 + f0;
            const float* Vr = Kr + 256;
#pragma unroll
            for (int i=0;i<4;i++){
                float4 kv = *(const float4*)(Kr + i*4);
                Ks[row*KS_STRIDE + f0 + i*4 + 0] = f2tf(kv.x);
                Ks[row*KS_STRIDE + f0 + i*4 + 1] = f2tf(kv.y);
                Ks[row*KS_STRIDE + f0 + i*4 + 2] = f2tf(kv.z);
                Ks[row*KS_STRIDE + f0 + i*4 + 3] = f2tf(kv.w);
                float4 vv = *(const float4*)(Vr + i*4);
                Vs[row*VS_STRIDE + f0 + i*4 + 0] = f2tf(vv.x);
                Vs[row*VS_STRIDE + f0 + i*4 + 1] = f2tf(vv.y);
                Vs[row*VS_STRIDE + f0 + i*4 + 2] = f2tf(vv.z);
                Vs[row*VS_STRIDE + f0 + i*4 + 3] = f2tf(vv.w);
            }
        }
        __syncthreads();

        // S = Q @ K^T (per warp: 16 x 64)
        float s[8][4];
#pragma unroll
        for (int nt=0;nt<8;nt++)
#pragma unroll
        for (int i=0;i<4;i++) s[nt][i] = 0.f;
#pragma unroll
        for (int kt=0;kt<8;kt++){
#pragma unroll
            for (int nt=0;nt<8;nt++){
                unsigned b0 = Ks[(nt*8+r)*KS_STRIDE + kt*8 + cq];
                unsigned b1 = Ks[(nt*8+r)*KS_STRIDE + kt*8 + cq + 4];
                mma_tf32(s[nt], qf[kt], b0, b1);
            }
        }

        // online softmax (rows r and r+8; row fully inside quad group)
        float mx_lo = -1e30f, mx_hi = -1e30f;
#pragma unroll
        for (int nt=0;nt<8;nt++){
            mx_lo = fmaxf(mx_lo, fmaxf(s[nt][0], s[nt][1]));
            mx_hi = fmaxf(mx_hi, fmaxf(s[nt][2], s[nt][3]));
        }
        mx_lo = fmaxf(mx_lo, __shfl_xor_sync(0xffffffffu, mx_lo, 1));
        mx_lo = fmaxf(mx_lo, __shfl_xor_sync(0xffffffffu, mx_lo, 2));
        mx_hi = fmaxf(mx_hi, __shfl_xor_sync(0xffffffffu, mx_hi, 1));
        mx_hi = fmaxf(mx_hi, __shfl_xor_sync(0xffffffffu, mx_hi, 2));

        float mn_lo = fmaxf(m_lo, mx_lo), mn_hi = fmaxf(m_hi, mx_hi);
        float f_lo = expf(m_lo - mn_lo),  f_hi = expf(m_hi - mn_hi);
        float rs_lo = 0.f, rs_hi = 0.f;
#pragma unroll
        for (int nt=0;nt<8;nt++){
            float p0 = expf(s[nt][0]-mn_lo), p1 = expf(s[nt][1]-mn_lo);
            float p2 = expf(s[nt][2]-mn_hi), p3 = expf(s[nt][3]-mn_hi);
            rs_lo += p0 + p1; rs_hi += p2 + p3;
            int cc = nt*8 + 2*cq;
            Psb[r*PS_STRIDE + cc]       = f2tf(p0);
            Psb[r*PS_STRIDE + cc + 1]   = f2tf(p1);
            Psb[(r+8)*PS_STRIDE + cc]   = f2tf(p2);
            Psb[(r+8)*PS_STRIDE + cc+1] = f2tf(p3);
        }
        rs_lo += __shfl_xor_sync(0xffffffffu, rs_lo, 1);
        rs_lo += __shfl_xor_sync(0xffffffffu, rs_lo, 2);
        rs_hi += __shfl_xor_sync(0xffffffffu, rs_hi, 1);
        rs_hi += __shfl_xor_sync(0xffffffffu, rs_hi, 2);
        l_lo = l_lo*f_lo + rs_lo;  m_lo = mn_lo;
        l_hi = l_hi*f_hi + rs_hi;  m_hi = mn_hi;
#pragma unroll
        for (int dt=0;dt<8;dt++){
            oacc[dt][0]*=f_lo; oacc[dt][1]*=f_lo;
            oacc[dt][2]*=f_hi; oacc[dt][3]*=f_hi;
        }
        __syncwarp();

        // O += P @ V
#pragma unroll
        for (int kt=0;kt<8;kt++){
            unsigned a[4];
            a[0] = Psb[r*PS_STRIDE     + kt*8 + cq];
            a[1] = Psb[(r+8)*PS_STRIDE + kt*8 + cq];
            a[2] = Psb[r*PS_STRIDE     + kt*8 + cq + 4];
            a[3] = Psb[(r+8)*PS_STRIDE + kt*8 + cq + 4];
#pragma unroll
            for (int dt=0;dt<8;dt++){
                unsigned b0 = Vs[(kt*8+cq)*VS_STRIDE   + dt*8 + r];
                unsigned b1 = Vs[(kt*8+cq+4)*VS_STRIDE + dt*8 + r];
                mma_tf32(oacc[dt], a, b0, b1);
            }
        }
    }

    // epilogue: O / l  -> attnO [N,256] at head column
    float il_lo = 1.f/l_lo, il_hi = 1.f/l_hi;
    float* Ob  = o + (size_t)(b*512 + q0 + w*16 + r)*256 + h*64;
    float* Ob2 = Ob + (size_t)8*256;
#pragma unroll
    for (int dt=0;dt<8;dt++){
        int cc = dt*8 + 2*cq;
        Ob[cc]    = oacc[dt][0]*il_lo;
        Ob[cc+1]  = oacc[dt][1]*il_lo;
        Ob2[cc]   = oacc[dt][2]*il_hi;
        Ob2[cc+1] = oacc[dt][3]*il_hi;
    }
}

// ---------------- GAT score kernels ----------------
__global__ void scores4_k(const float* __restrict__ h, const float* __restrict__ aS,
                          const float* __restrict__ aD, float* __restrict__ es,
                          float* __restrict__ ed){
    int w = (blockIdx.x*blockDim.x + threadIdx.x) >> 5;
    int lane = threadIdx.x & 31;
    if (w >= N_NODES) return;
    const float* hr = h + (size_t)w*256;
#pragma unroll
    for (int hh=0; hh<4; hh++){
        float v0 = hr[hh*64+lane], v1 = hr[hh*64+32+lane];
        float ps = v0*aS[hh*64+lane] + v1*aS[hh*64+32+lane];
        float pd = v0*aD[hh*64+lane] + v1*aD[hh*64+32+lane];
        ps = wsum(ps); pd = wsum(pd);
        if (lane == 0){ es[w*4+hh] = ps; ed[w*4+hh] = pd; }
    }
}
__global__ void scores1_k(const float* __restrict__ h, const float* __restrict__ aS,
                          const float* __restrict__ aD, float* __restrict__ es,
                          float* __restrict__ ed){
    int w = (blockIdx.x*blockDim.x + threadIdx.x) >> 5;
    int lane = threadIdx.x & 31;
    if (w >= N_NODES) return;
    const float* hr = h + (size_t)w*128;
    float ps = 0.f, pd = 0.f;
#pragma unroll
    for (int i=0;i<4;i++){
        int ch = lane + i*32;
        ps += hr[ch]*aS[ch];
        pd += hr[ch]*aD[ch];
    }
    ps = wsum(ps); pd = wsum(pd);
    if (lane == 0){ es[w] = ps; ed[w] = pd; }
}

// ---------------- GAT aggregate (warp per dst node) ----------------
__global__ void agg4_k(const float* __restrict__ hbuf, const float* __restrict__ es,
                       const float* __restrict__ ed, const int* __restrict__ rowptr,
                       const int* __restrict__ col, const float* __restrict__ bias,
                       float* __restrict__ out, int do_elu){
    int w = (blockIdx.x*blockDim.x + threadIdx.x) >> 5;
    int lane = threadIdx.x & 31;
    if (w >= N_NODES) return;
    float edv[4];
#pragma unroll
    for (int h=0;h<4;h++) edv[h] = ed[w*4+h];
    int beg = rowptr[w], end = rowptr[w+1];

    float mx[4] = {-1e30f,-1e30f,-1e30f,-1e30f};
    for (int e = beg + lane; e < end; e += 32){
        int s = col[e];
#pragma unroll
        for (int h=0;h<4;h++){
            float v = es[s*4+h] + edv[h];
            v = (v >= 0.f) ? v : 0.2f*v;
            mx[h] = fmaxf(mx[h], v);
        }
    }
#pragma unroll
    for (int h=0;h<4;h++) mx[h] = wmax(mx[h]);

    float acc[8] = {0,0,0,0,0,0,0,0};
    float sh[4]  = {0,0,0,0};
    for (int e = beg; e < end; e++){
        int s = col[e];
        float pl = 0.f;
        if (lane < 4){
            float v = es[s*4+lane] + edv[lane];
            v = (v >= 0.f) ? v : 0.2f*v;
            pl = expf(v - mx[lane]);
        }
        float p[4];
#pragma unroll
        for (int h=0;h<4;h++) p[h] = __shfl_sync(0xffffffffu, pl, h);
#pragma unroll
        for (int h=0;h<4;h++) sh[h] += p[h];
        const float* hr = hbuf + (size_t)s*256;
#pragma unroll
        for (int i=0;i<8;i++){
            int ch = lane + i*32;
            acc[i] += p[i>>1] * hr[ch];
        }
    }
#pragma unroll
    for (int i=0;i<8;i++){
        int ch = lane + i*32;
        float v = acc[i]/sh[i>>1] + bias[ch];
        if (do_elu) v = (v > 0.f) ? v : expm1f(v);
        out[(size_t)w*256 + ch] = v;
    }
}
__global__ void agg1_k(const float* __restrict__ hbuf, const float* __restrict__ es,
                       const float* __restrict__ ed, const int* __restrict__ rowptr,
                       const int* __restrict__ col, const float* __restrict__ bias,
                       float* __restrict__ out){
    int w = (blockIdx.x*blockDim.x + threadIdx.x) >> 5;
    int lane = threadIdx.x & 31;
    if (w >= N_NODES) return;
    float edv = ed[w];
    int beg = rowptr[w], end = rowptr[w+1];

    float mx = -1e30f;
    for (int e = beg + lane; e < end; e += 32){
        float v = es[col[e]] + edv;
        v = (v >= 0.f) ? v : 0.2f*v;
        mx = fmaxf(mx, v);
    }
    mx = wmax(mx);

    float acc[4] = {0,0,0,0};
    float ssum = 0.f;
    for (int e = beg; e < end; e++){
        int s = col[e];
        float v = es[s] + edv;
        v = (v >= 0.f) ? v : 0.2f*v;
        float p = expf(v - mx);
        ssum += p;
        const float* hr = hbuf + (size_t)s*128;
#pragma unroll
        for (int i=0;i<4;i++){
            int ch = lane + i*32;
            acc[i] += p * hr[ch];
        }
    }
#pragma unroll
    for (int i=0;i<4;i++){
        int ch = lane + i*32;
        out[(size_t)w*128 + ch] = acc[i]/ssum + bias[ch];
    }
}

// ---------------- residual + layernorm ----------------
__global__ void ln_k(const float* __restrict__ att, const float* __restrict__ x2,
                     const float* __restrict__ gamma, const float* __restrict__ beta,
                     float* __restrict__ out){
    int w = (blockIdx.x*blockDim.x + threadIdx.x) >> 5;
    int lane = threadIdx.x & 31;
    if (w >= N_NODES) return;
    float v[8];
    float s = 0.f;
#pragma unroll
    for (int i=0;i<8;i++){
        int ch = lane + i*32;
        v[i] = att[(size_t)w*256+ch] + x2[(size_t)w*256+ch];
        s += v[i];
    }
    s = wsum(s);
    float mean = s * (1.f/256.f);
    float sq = 0.f;
#pragma unroll
    for (int i=0;i<8;i++){ float d = v[i]-mean; sq += d*d; }
    sq = wsum(sq);
    float rstd = rsqrtf(sq*(1.f/256.f) + 1e-5f);
#pragma unroll
    for (int i=0;i<8;i++){
        int ch = lane + i*32;
        out[(size_t)w*256+ch] = (v[i]-mean)*rstd*gamma[ch] + beta[ch];
    }
}

// ---------------- host ----------------
static void launch_gemm(bool transb,
    const float* A,int lda,long long a1,long long a2,
    const float* B,int ldb,long long b1,long long b2,
    float* C,int ldc,long long c1,long long c2,
    const float* bias,int M,int Nn,int K,float alpha,int nz,int ZD)
{
    dim3 g((Nn+127)/128, (M+127)/128, nz);
    if (transb)
        gemm_tc<true><<<g,256>>>(A,lda,a1,a2,B,ldb,b1,b2,C,ldc,c1,c2,bias,Nn,K,alpha,ZD);
    else
        gemm_tc<false><<<g,256>>>(A,lda,a1,a2,B,ldb,b1,b2,C,ldc,c1,c2,bias,Nn,K,alpha,ZD);
}

extern "C" void kernel_launch(void* const* d_in, const int* in_sizes, int n_in,
                              void* d_out, int out_size)
{
    const float* x   = (const float*)d_in[0];
    const int*   ei  = (const int*)d_in[1];     // int32 (JAX default, no x64)
    const float* W1  = (const float*)d_in[3];
    const float* aS1 = (const float*)d_in[4];
    const float* aD1 = (const float*)d_in[5];
    const float* b1  = (const float*)d_in[6];
    const float* W2  = (const float*)d_in[7];
    const float* aS2 = (const float*)d_in[8];
    const float* aD2 = (const float*)d_in[9];
    const float* b2  = (const float*)d_in[10];
    const float* W3  = (const float*)d_in[11];
    const float* aS3 = (const float*)d_in[12];
    const float* aD3 = (const float*)d_in[13];
    const float* b3  = (const float*)d_in[14];
    const float* Wi  = (const float*)d_in[15];
    const float* bi  = (const float*)d_in[16];
    const float* Wo  = (const float*)d_in[17];
    const float* bo  = (const float*)d_in[18];
    const float* gam = (const float*)d_in[19];
    const float* bet = (const float*)d_in[20];
    float* out = (float*)d_out;

    float *h_, *x1_, *x2_, *qkv_, *attnO_, *att_, *x2a_, *es_, *ed_;
    int *cnt_, *rowptr_, *cursor_, *col_;
    cudaGetSymbolAddress((void**)&h_,     g_h);
    cudaGetSymbolAddress((void**)&x1_,    g_x1);
    cudaGetSymbolAddress((void**)&x2_,    g_x2);
    cudaGetSymbolAddress((void**)&qkv_,   g_qkv);
    cudaGetSymbolAddress((void**)&attnO_, g_attnO);
    cudaGetSymbolAddress((void**)&att_,   g_att);
    cudaGetSymbolAddress((void**)&x2a_,   g_x2a);
    cudaGetSymbolAddress((void**)&es_,    g_es);
    cudaGetSymbolAddress((void**)&ed_,    g_ed);
    cudaGetSymbolAddress((void**)&cnt_,   g_cnt);
    cudaGetSymbolAddress((void**)&rowptr_,g_rowptr);
    cudaGetSymbolAddress((void**)&cursor_,g_cursor);
    cudaGetSymbolAddress((void**)&col_,   g_col);

    cudaFuncSetAttribute(flash_k, cudaFuncAttributeMaxDynamicSharedMemorySize, FLASH_SMEM);

    // ---- CSR by dst ----
    init_cnt_k<<<N_NODES/256,256>>>(cnt_);
    hist_k<<<E_EDGES/256,256>>>(ei, cnt_);
    scan_k<<<1,1024>>>(cnt_, rowptr_, cursor_);
    scat_k<<<E_EDGES/256,256>>>(ei, cursor_, col_);
    selfloop_k<<<N_NODES/256,256>>>(cursor_, col_);

    const int WBLK = 4096;  // warp-per-node kernels: 8 warps/block

    // ---- GAT layer 1 ----
    launch_gemm(false, x,128,0,0, W1,256,0,0, h_,256,0,0, nullptr, N_NODES,256,128, 1.f, 1,1);
    scores4_k<<<WBLK,256>>>(h_, aS1, aD1, es_, ed_);
    agg4_k<<<WBLK,256>>>(h_, es_, ed_, rowptr_, col_, b1, x1_, 1);

    // ---- GAT layer 2 ----
    launch_gemm(false, x1_,256,0,0, W2,256,0,0, h_,256,0,0, nullptr, N_NODES,256,256, 1.f, 1,1);
    scores4_k<<<WBLK,256>>>(h_, aS2, aD2, es_, ed_);
    agg4_k<<<WBLK,256>>>(h_, es_, ed_, rowptr_, col_, b2, x2_, 1);

    // ---- MHA: QKV projection, fused flash attention, out projection ----
    launch_gemm(true,  x2_,256,0,0, Wi,256,0,0, qkv_,768,0,0, bi, N_NODES,768,256, 1.f, 1,1);
    flash_k<<<dim3(4,256),256,FLASH_SMEM>>>(qkv_, attnO_);
    launch_gemm(true,  attnO_,256,0,0, Wo,256,0,0, att_,256,0,0, bo, N_NODES,256,256, 1.f, 1,1);

    // ---- residual + LN ----
    ln_k<<<WBLK,256>>>(att_, x2_, gam, bet, x2a_);

    // ---- GAT layer 3 ----
    launch_gemm(false, x2a_,256,0,0, W3,128,0,0, h_,128,0,0, nullptr, N_NODES,128,256, 1.f, 1,1);
    scores1_k<<<WBLK,256>>>(h_, aS3, aD3, es_, ed_);
    agg1_k<<<WBLK,256>>>(h_, es_, ed_, rowptr_, col_, b3, out);
}

// round 5
// speedup vs baseline: 2.5474x; 1.0582x over previous
#include <cuda_runtime.h>
#include <math.h>

#define N_NODES 32768
#define E_EDGES 524288
#define E_TOT   (E_EDGES + N_NODES)

// ---------------- scratch (device globals; no runtime allocation) ----------------
__device__ float g_h    [(size_t)N_NODES*256];
__device__ float g_x1   [(size_t)N_NODES*256];
__device__ float g_x2   [(size_t)N_NODES*256];
__device__ float g_qkv  [(size_t)N_NODES*768];
__device__ float g_attnO[(size_t)N_NODES*256];
__device__ float g_att  [(size_t)N_NODES*256];
__device__ float g_x2a  [(size_t)N_NODES*256];
__device__ float g_es   [N_NODES*4];
__device__ float g_ed   [N_NODES*4];
__device__ int   g_cnt   [N_NODES];
__device__ int   g_rowptr[N_NODES+1];
__device__ int   g_cursor[N_NODES];
__device__ int   g_col   [E_TOT];

// ---------------- warp reduce helpers ----------------
__device__ __forceinline__ float wsum(float v){
#pragma unroll
    for (int o=16;o;o>>=1) v += __shfl_xor_sync(0xffffffffu, v, o);
    return v;
}

// ---------------- CSR build (edge_index is int32) ----------------
__global__ void init_cnt_k(int* cnt){
    int i = blockIdx.x*blockDim.x + threadIdx.x;
    if (i < N_NODES) cnt[i] = 1;      // self-loop pre-counted
}
__global__ void hist_k(const int* __restrict__ ei, int* cnt){
    int e = blockIdx.x*blockDim.x + threadIdx.x;
    if (e < E_EDGES){
        int d = ei[E_EDGES + e];
        if (d >= 0 && d < N_NODES) atomicAdd(&cnt[d], 1);
    }
}
// 1 block, 1024 threads, 32 values per thread
__global__ void scan_k(const int* __restrict__ cnt, int* rowptr, int* cursor){
    __shared__ int wsums[32];
    int t = threadIdx.x, lane = t & 31, wid = t >> 5;
    int base = t*32;
    int vals[32];
    int s = 0;
#pragma unroll
    for (int i=0;i<32;i++){ vals[i] = cnt[base+i]; s += vals[i]; }
    int x = s;
#pragma unroll
    for (int o=1;o<32;o<<=1){
        int y = __shfl_up_sync(0xffffffffu, x, o);
        if (lane >= o) x += y;
    }
    if (lane == 31) wsums[wid] = x;
    __syncthreads();
    if (wid == 0){
        int y = wsums[lane];
#pragma unroll
        for (int o=1;o<32;o<<=1){
            int z = __shfl_up_sync(0xffffffffu, y, o);
            if (lane >= o) y += z;
        }
        wsums[lane] = y;
    }
    __syncthreads();
    int excl = x - s + (wid ? wsums[wid-1] : 0);
    int run = excl;
#pragma unroll
    for (int i=0;i<32;i++){
        rowptr[base+i] = run; cursor[base+i] = run; run += vals[i];
    }
    if (t == 1023) rowptr[N_NODES] = run;
}
__global__ void scat_k(const int* __restrict__ ei, int* cursor, int* col){
    int e = blockIdx.x*blockDim.x + threadIdx.x;
    if (e < E_EDGES){
        int d = ei[E_EDGES + e];
        int s = ei[e];
        if (d >= 0 && d < N_NODES){
            int p = atomicAdd(&cursor[d], 1);
            col[p] = s;
        }
    }
}
__global__ void selfloop_k(int* cursor, int* col){
    int n = blockIdx.x*blockDim.x + threadIdx.x;
    if (n < N_NODES){
        int p = atomicAdd(&cursor[n], 1);
        col[p] = n;
    }
}

// ---------------- tf32 helpers ----------------
__device__ __forceinline__ unsigned f2tf(float f){
    unsigned u; asm("cvt.rna.tf32.f32 %0, %1;" : "=r"(u) : "f"(f)); return u;
}
__device__ __forceinline__ void mma_tf32(float* c, const unsigned* a, unsigned b0, unsigned b1){
    asm volatile(
      "mma.sync.aligned.m16n8k8.row.col.f32.tf32.tf32.f32 "
      "{%0,%1,%2,%3}, {%4,%5,%6,%7}, {%8,%9}, {%0,%1,%2,%3};\n"
      : "+f"(c[0]), "+f"(c[1]), "+f"(c[2]), "+f"(c[3])
      : "r"(a[0]),"r"(a[1]),"r"(a[2]),"r"(a[3]), "r"(b0),"r"(b1));
}

// ---------------- tf32 tensor-core GEMM (register double-buffered) ----------------
template<bool TRANSB>
__global__ __launch_bounds__(256) void gemm_tc(
    const float* __restrict__ A, int lda, long long sA1, long long sA2,
    const float* __restrict__ B, int ldb, long long sB1, long long sB2,
    float* __restrict__ C, int ldc, long long sC1, long long sC2,
    const float* __restrict__ bias, int Nn, int K, float alpha, int ZD)
{
    int z = blockIdx.z;
    long long z1 = z % ZD, z2 = z / ZD;
    A += z1*sA1 + z2*sA2;
    B += z1*sB1 + z2*sB2;
    C += z1*sC1 + z2*sC2;

    __shared__ unsigned As[16][136];
    __shared__ unsigned Bs[16][136];

    const int tid  = threadIdx.x;
    const int lane = tid & 31, warp = tid >> 5;
    const int m0 = blockIdx.y*128, n0 = blockIdx.x*128;
    const int wm = (warp & 1)*64, wn = (warp >> 1)*32;
    const int r = lane >> 2, cq = lane & 3;

    // A-load indices: fid = tid + l*256 -> m = fid>>2, c4 = (fid&3)*4
    const int am[2]  = { tid>>2, (tid+256)>>2 };
    const int ac4[2] = { (tid&3)*4, (tid&3)*4 };
    float4 ra[2], rb[2];

    auto loadA = [&](int k0){
#pragma unroll
        for (int l=0;l<2;l++)
            ra[l] = *(const float4*)(A + (size_t)(m0+am[l])*lda + k0 + ac4[l]);
    };
    auto loadB = [&](int k0){
        if (!TRANSB){
#pragma unroll
            for (int l=0;l<2;l++){
                int fid = tid + l*256;
                int k = fid >> 5, n4 = (fid & 31)*4;
                rb[l] = make_float4(0.f,0.f,0.f,0.f);
                if (n0+n4 < Nn) rb[l] = *(const float4*)(B + (size_t)(k0+k)*ldb + n0 + n4);
            }
        } else {
#pragma unroll
            for (int l=0;l<2;l++){
                int fid = tid + l*256;
                int n = fid >> 2, k4 = (fid & 3)*4;
                rb[l] = make_float4(0.f,0.f,0.f,0.f);
                if (n0+n < Nn) rb[l] = *(const float4*)(B + (size_t)(n0+n)*ldb + k0 + k4);
            }
        }
    };

    float acc[4][4][4];
#pragma unroll
    for (int a=0;a<4;a++)
#pragma unroll
    for (int b=0;b<4;b++)
#pragma unroll
    for (int c=0;c<4;c++) acc[a][b][c] = 0.f;

    loadA(0); loadB(0);

    for (int k0 = 0; k0 < K; k0 += 16){
        // store staged regs to smem (cvt to tf32)
#pragma unroll
        for (int l=0;l<2;l++){
            int m = am[l], c4 = ac4[l];
            As[c4+0][m]=f2tf(ra[l].x); As[c4+1][m]=f2tf(ra[l].y);
            As[c4+2][m]=f2tf(ra[l].z); As[c4+3][m]=f2tf(ra[l].w);
        }
        if (!TRANSB){
#pragma unroll
            for (int l=0;l<2;l++){
                int fid = tid + l*256;
                int k = fid >> 5, n4 = (fid & 31)*4;
                Bs[k][n4+0]=f2tf(rb[l].x); Bs[k][n4+1]=f2tf(rb[l].y);
                Bs[k][n4+2]=f2tf(rb[l].z); Bs[k][n4+3]=f2tf(rb[l].w);
            }
        } else {
#pragma unroll
            for (int l=0;l<2;l++){
                int fid = tid + l*256;
                int n = fid >> 2, k4 = (fid & 3)*4;
                Bs[k4+0][n]=f2tf(rb[l].x); Bs[k4+1][n]=f2tf(rb[l].y);
                Bs[k4+2][n]=f2tf(rb[l].z); Bs[k4+3][n]=f2tf(rb[l].w);
            }
        }
        __syncthreads();
        // prefetch next tile (overlaps with MMAs below)
        if (k0 + 16 < K){ loadA(k0+16); loadB(k0+16); }
#pragma unroll
        for (int ks=0; ks<2; ks++){
            const int kb = ks*8;
            unsigned af[4][4], bf[4][2];
#pragma unroll
            for (int mt=0;mt<4;mt++){
                int mb = wm + mt*16;
                af[mt][0] = As[kb+cq  ][mb+r];
                af[mt][1] = As[kb+cq  ][mb+r+8];
                af[mt][2] = As[kb+cq+4][mb+r];
                af[mt][3] = As[kb+cq+4][mb+r+8];
            }
#pragma unroll
            for (int nt=0;nt<4;nt++){
                int nb = wn + nt*8;
                bf[nt][0] = Bs[kb+cq  ][nb+r];
                bf[nt][1] = Bs[kb+cq+4][nb+r];
            }
#pragma unroll
            for (int mt=0;mt<4;mt++)
#pragma unroll
            for (int nt=0;nt<4;nt++)
                mma_tf32(acc[mt][nt], af[mt], bf[nt][0], bf[nt][1]);
        }
        __syncthreads();
    }

#pragma unroll
    for (int mt=0;mt<4;mt++){
        int row0 = m0 + wm + mt*16 + r;
#pragma unroll
        for (int nt=0;nt<4;nt++){
            int col = n0 + wn + nt*8 + 2*cq;
            if (col < Nn){
                float bv0 = bias ? bias[col]   : 0.f;
                float bv1 = bias ? bias[col+1] : 0.f;
                C[(size_t)row0*ldc + col]       = acc[mt][nt][0]*alpha + bv0;
                C[(size_t)row0*ldc + col + 1]   = acc[mt][nt][1]*alpha + bv1;
                C[(size_t)(row0+8)*ldc + col]   = acc[mt][nt][2]*alpha + bv0;
                C[(size_t)(row0+8)*ldc + col+1] = acc[mt][nt][3]*alpha + bv1;
            }
        }
    }
}

// ---------------- fused flash attention ----------------
#define KS_STRIDE 68
#define VS_STRIDE 72
#define PS_STRIDE 68
#define FLASH_SMEM ((64*KS_STRIDE + 64*VS_STRIDE + 8*16*PS_STRIDE)*4)

__global__ __launch_bounds__(256,1) void flash_k(const float* __restrict__ qkv,
                                                 float* __restrict__ o)
{
    extern __shared__ unsigned sm[];
    unsigned* Ks = sm;
    unsigned* Vs = Ks + 64*KS_STRIDE;
    unsigned* Ps = Vs + 64*VS_STRIDE;

    const int qt = blockIdx.x, bh = blockIdx.y;
    const int b = bh >> 2, h = bh & 3;
    const int tid = threadIdx.x, w = tid >> 5, lane = tid & 31;
    const int r = lane >> 2, cq = lane & 3;
    const int q0 = qt*128;
    unsigned* Psb = Ps + w*16*PS_STRIDE;

    const float* Q = qkv + (size_t)(b*512 + q0 + w*16)*768 + h*64;
    unsigned qf[8][4];
#pragma unroll
    for (int kt=0;kt<8;kt++){
        int c0 = kt*8 + cq;
        qf[kt][0] = f2tf(0.125f * Q[(size_t)r*768     + c0]);
        qf[kt][1] = f2tf(0.125f * Q[(size_t)(r+8)*768 + c0]);
        qf[kt][2] = f2tf(0.125f * Q[(size_t)r*768     + c0+4]);
        qf[kt][3] = f2tf(0.125f * Q[(size_t)(r+8)*768 + c0+4]);
    }

    float oacc[8][4];
#pragma unroll
    for (int dt=0;dt<8;dt++)
#pragma unroll
    for (int i=0;i<4;i++) oacc[dt][i] = 0.f;
    float m_lo=-1e30f, m_hi=-1e30f, l_lo=0.f, l_hi=0.f;

    for (int c=0;c<8;c++){
        __syncthreads();
        {
            int row = tid >> 2, f0 = (tid & 3)*16;
            const float* Kr = qkv + (size_t)(b*512 + c*64 + row)*768 + 256 + h*64 + f0;
            const float* Vr = Kr + 256;
#pragma unroll
            for (int i=0;i<4;i++){
                float4 kv = *(const float4*)(Kr + i*4);
                Ks[row*KS_STRIDE + f0 + i*4 + 0] = f2tf(kv.x);
                Ks[row*KS_STRIDE + f0 + i*4 + 1] = f2tf(kv.y);
                Ks[row*KS_STRIDE + f0 + i*4 + 2] = f2tf(kv.z);
                Ks[row*KS_STRIDE + f0 + i*4 + 3] = f2tf(kv.w);
                float4 vv = *(const float4*)(Vr + i*4);
                Vs[row*VS_STRIDE + f0 + i*4 + 0] = f2tf(vv.x);
                Vs[row*VS_STRIDE + f0 + i*4 + 1] = f2tf(vv.y);
                Vs[row*VS_STRIDE + f0 + i*4 + 2] = f2tf(vv.z);
                Vs[row*VS_STRIDE + f0 + i*4 + 3] = f2tf(vv.w);
            }
        }
        __syncthreads();

        float s[8][4];
#pragma unroll
        for (int nt=0;nt<8;nt++)
#pragma unroll
        for (int i=0;i<4;i++) s[nt][i] = 0.f;
#pragma unroll
        for (int kt=0;kt<8;kt++){
#pragma unroll
            for (int nt=0;nt<8;nt++){
                unsigned b0 = Ks[(nt*8+r)*KS_STRIDE + kt*8 + cq];
                unsigned b1 = Ks[(nt*8+r)*KS_STRIDE + kt*8 + cq + 4];
                mma_tf32(s[nt], qf[kt], b0, b1);
            }
        }

        float mx_lo = -1e30f, mx_hi = -1e30f;
#pragma unroll
        for (int nt=0;nt<8;nt++){
            mx_lo = fmaxf(mx_lo, fmaxf(s[nt][0], s[nt][1]));
            mx_hi = fmaxf(mx_hi, fmaxf(s[nt][2], s[nt][3]));
        }
        mx_lo = fmaxf(mx_lo, __shfl_xor_sync(0xffffffffu, mx_lo, 1));
        mx_lo = fmaxf(mx_lo, __shfl_xor_sync(0xffffffffu, mx_lo, 2));
        mx_hi = fmaxf(mx_hi, __shfl_xor_sync(0xffffffffu, mx_hi, 1));
        mx_hi = fmaxf(mx_hi, __shfl_xor_sync(0xffffffffu, mx_hi, 2));

        float mn_lo = fmaxf(m_lo, mx_lo), mn_hi = fmaxf(m_hi, mx_hi);
        float f_lo = expf(m_lo - mn_lo),  f_hi = expf(m_hi - mn_hi);
        float rs_lo = 0.f, rs_hi = 0.f;
#pragma unroll
        for (int nt=0;nt<8;nt++){
            float p0 = expf(s[nt][0]-mn_lo), p1 = expf(s[nt][1]-mn_lo);
            float p2 = expf(s[nt][2]-mn_hi), p3 = expf(s[nt][3]-mn_hi);
            rs_lo += p0 + p1; rs_hi += p2 + p3;
            int cc = nt*8 + 2*cq;
            Psb[r*PS_STRIDE + cc]       = f2tf(p0);
            Psb[r*PS_STRIDE + cc + 1]   = f2tf(p1);
            Psb[(r+8)*PS_STRIDE + cc]   = f2tf(p2);
            Psb[(r+8)*PS_STRIDE + cc+1] = f2tf(p3);
        }
        rs_lo += __shfl_xor_sync(0xffffffffu, rs_lo, 1);
        rs_lo += __shfl_xor_sync(0xffffffffu, rs_lo, 2);
        rs_hi += __shfl_xor_sync(0xffffffffu, rs_hi, 1);
        rs_hi += __shfl_xor_sync(0xffffffffu, rs_hi, 2);
        l_lo = l_lo*f_lo + rs_lo;  m_lo = mn_lo;
        l_hi = l_hi*f_hi + rs_hi;  m_hi = mn_hi;
#pragma unroll
        for (int dt=0;dt<8;dt++){
            oacc[dt][0]*=f_lo; oacc[dt][1]*=f_lo;
            oacc[dt][2]*=f_hi; oacc[dt][3]*=f_hi;
        }
        __syncwarp();

#pragma unroll
        for (int kt=0;kt<8;kt++){
            unsigned a[4];
            a[0] = Psb[r*PS_STRIDE     + kt*8 + cq];
            a[1] = Psb[(r+8)*PS_STRIDE + kt*8 + cq];
            a[2] = Psb[r*PS_STRIDE     + kt*8 + cq + 4];
            a[3] = Psb[(r+8)*PS_STRIDE + kt*8 + cq + 4];
#pragma unroll
            for (int dt=0;dt<8;dt++){
                unsigned b0 = Vs[(kt*8+cq)*VS_STRIDE   + dt*8 + r];
                unsigned b1 = Vs[(kt*8+cq+4)*VS_STRIDE + dt*8 + r];
                mma_tf32(oacc[dt], a, b0, b1);
            }
        }
    }

    float il_lo = 1.f/l_lo, il_hi = 1.f/l_hi;
    float* Ob  = o + (size_t)(b*512 + q0 + w*16 + r)*256 + h*64;
    float* Ob2 = Ob + (size_t)8*256;
#pragma unroll
    for (int dt=0;dt<8;dt++){
        int cc = dt*8 + 2*cq;
        Ob[cc]    = oacc[dt][0]*il_lo;
        Ob[cc+1]  = oacc[dt][1]*il_lo;
        Ob2[cc]   = oacc[dt][2]*il_hi;
        Ob2[cc+1] = oacc[dt][3]*il_hi;
    }
}

// ---------------- GAT score kernels (float4) ----------------
__global__ void scores4_k(const float* __restrict__ h, const float* __restrict__ aS,
                          const float* __restrict__ aD, float* __restrict__ es,
                          float* __restrict__ ed){
    int w = (blockIdx.x*blockDim.x + threadIdx.x) >> 5;
    int lane = threadIdx.x & 31;
    if (w >= N_NODES) return;
    int head = lane >> 3;
    const float4* hr = (const float4*)(h + (size_t)w*256 + lane*8);
    const float4* s4 = (const float4*)(aS + lane*8);
    const float4* d4 = (const float4*)(aD + lane*8);
    float4 a = hr[0], b = hr[1];
    float4 sa = s4[0], sb = s4[1];
    float4 da = d4[0], db = d4[1];
    float ps = a.x*sa.x + a.y*sa.y + a.z*sa.z + a.w*sa.w
             + b.x*sb.x + b.y*sb.y + b.z*sb.z + b.w*sb.w;
    float pd = a.x*da.x + a.y*da.y + a.z*da.z + a.w*da.w
             + b.x*db.x + b.y*db.y + b.z*db.z + b.w*db.w;
#pragma unroll
    for (int o=1;o<8;o<<=1){
        ps += __shfl_xor_sync(0xffffffffu, ps, o);
        pd += __shfl_xor_sync(0xffffffffu, pd, o);
    }
    if ((lane & 7) == 0){ es[w*4+head] = ps; ed[w*4+head] = pd; }
}
__global__ void scores1_k(const float* __restrict__ h, const float* __restrict__ aS,
                          const float* __restrict__ aD, float* __restrict__ es,
                          float* __restrict__ ed){
    int w = (blockIdx.x*blockDim.x + threadIdx.x) >> 5;
    int lane = threadIdx.x & 31;
    if (w >= N_NODES) return;
    const float4* hr = (const float4*)(h + (size_t)w*128 + lane*4);
    const float4* s4 = (const float4*)(aS + lane*4);
    const float4* d4 = (const float4*)(aD + lane*4);
    float4 a = hr[0], sa = s4[0], da = d4[0];
    float ps = a.x*sa.x + a.y*sa.y + a.z*sa.z + a.w*sa.w;
    float pd = a.x*da.x + a.y*da.y + a.z*da.z + a.w*da.w;
    ps = wsum(ps); pd = wsum(pd);
    if (lane == 0){ es[w] = ps; ed[w] = pd; }
}

// ---------------- GAT aggregate (warp per dst, no max pass, float4 gather) --------
__global__ void agg4_k(const float* __restrict__ hbuf, const float* __restrict__ es,
                       const float* __restrict__ ed, const int* __restrict__ rowptr,
                       const int* __restrict__ col, const float* __restrict__ bias,
                       float* __restrict__ out, int do_elu){
    int w = (blockIdx.x*blockDim.x + threadIdx.x) >> 5;
    int lane = threadIdx.x & 31;
    if (w >= N_NODES) return;
    const int head = lane >> 3;
    float edv = ed[w*4+head];
    int beg = rowptr[w], end = rowptr[w+1];

    float acc[8] = {0,0,0,0,0,0,0,0};
    float sh = 0.f;

    // software pipeline: compute p for edge e+1 while gathering edge e
    int s = col[beg];
    float v = es[s*4+head] + edv;
    v = (v >= 0.f) ? v : 0.2f*v;
    float p = expf(v);

    for (int e = beg; e < end; e++){
        int s2 = 0; float p2 = 0.f;
        if (e + 1 < end){
            s2 = col[e+1];
            float vv = es[s2*4+head] + edv;
            vv = (vv >= 0.f) ? vv : 0.2f*vv;
            p2 = expf(vv);
        }
        const float4* hr = (const float4*)(hbuf + (size_t)s*256 + lane*8);
        float4 a = hr[0], b = hr[1];
        acc[0] += p*a.x; acc[1] += p*a.y; acc[2] += p*a.z; acc[3] += p*a.w;
        acc[4] += p*b.x; acc[5] += p*b.y; acc[6] += p*b.z; acc[7] += p*b.w;
        sh += p;
        s = s2; p = p2;
    }

    float inv = 1.f/sh;
    const float4* b4 = (const float4*)(bias + lane*8);
    float4 bb0 = b4[0], bb1 = b4[1];
    float4 o0, o1;
    o0.x = acc[0]*inv + bb0.x; o0.y = acc[1]*inv + bb0.y;
    o0.z = acc[2]*inv + bb0.z; o0.w = acc[3]*inv + bb0.w;
    o1.x = acc[4]*inv + bb1.x; o1.y = acc[5]*inv + bb1.y;
    o1.z = acc[6]*inv + bb1.z; o1.w = acc[7]*inv + bb1.w;
    if (do_elu){
        o0.x = (o0.x > 0.f) ? o0.x : expm1f(o0.x);
        o0.y = (o0.y > 0.f) ? o0.y : expm1f(o0.y);
        o0.z = (o0.z > 0.f) ? o0.z : expm1f(o0.z);
        o0.w = (o0.w > 0.f) ? o0.w : expm1f(o0.w);
        o1.x = (o1.x > 0.f) ? o1.x : expm1f(o1.x);
        o1.y = (o1.y > 0.f) ? o1.y : expm1f(o1.y);
        o1.z = (o1.z > 0.f) ? o1.z : expm1f(o1.z);
        o1.w = (o1.w > 0.f) ? o1.w : expm1f(o1.w);
    }
    float4* ov = (float4*)(out + (size_t)w*256 + lane*8);
    ov[0] = o0; ov[1] = o1;
}
__global__ void agg1_k(const float* __restrict__ hbuf, const float* __restrict__ es,
                       const float* __restrict__ ed, const int* __restrict__ rowptr,
                       const int* __restrict__ col, const float* __restrict__ bias,
                       float* __restrict__ out){
    int w = (blockIdx.x*blockDim.x + threadIdx.x) >> 5;
    int lane = threadIdx.x & 31;
    if (w >= N_NODES) return;
    float edv = ed[w];
    int beg = rowptr[w], end = rowptr[w+1];

    float acc[4] = {0,0,0,0};
    float sh = 0.f;

    int s = col[beg];
    float v = es[s] + edv;
    v = (v >= 0.f) ? v : 0.2f*v;
    float p = expf(v);

    for (int e = beg; e < end; e++){
        int s2 = 0; float p2 = 0.f;
        if (e + 1 < end){
            s2 = col[e+1];
            float vv = es[s2] + edv;
            vv = (vv >= 0.f) ? vv : 0.2f*vv;
            p2 = expf(vv);
        }
        float4 a = *(const float4*)(hbuf + (size_t)s*128 + lane*4);
        acc[0] += p*a.x; acc[1] += p*a.y; acc[2] += p*a.z; acc[3] += p*a.w;
        sh += p;
        s = s2; p = p2;
    }

    float inv = 1.f/sh;
    float4 bb = *(const float4*)(bias + lane*4);
    float4 o0;
    o0.x = acc[0]*inv + bb.x; o0.y = acc[1]*inv + bb.y;
    o0.z = acc[2]*inv + bb.z; o0.w = acc[3]*inv + bb.w;
    *(float4*)(out + (size_t)w*128 + lane*4) = o0;
}

// ---------------- residual + layernorm (float4) ----------------
__global__ void ln_k(const float* __restrict__ att, const float* __restrict__ x2,
                     const float* __restrict__ gamma, const float* __restrict__ beta,
                     float* __restrict__ out){
    int w = (blockIdx.x*blockDim.x + threadIdx.x) >> 5;
    int lane = threadIdx.x & 31;
    if (w >= N_NODES) return;
    const float4* a4 = (const float4*)(att + (size_t)w*256 + lane*8);
    const float4* x4 = (const float4*)(x2  + (size_t)w*256 + lane*8);
    float4 v0 = a4[0], v1 = a4[1], u0 = x4[0], u1 = x4[1];
    v0.x+=u0.x; v0.y+=u0.y; v0.z+=u0.z; v0.w+=u0.w;
    v1.x+=u1.x; v1.y+=u1.y; v1.z+=u1.z; v1.w+=u1.w;
    float s = v0.x+v0.y+v0.z+v0.w+v1.x+v1.y+v1.z+v1.w;
    s = wsum(s);
    float mean = s * (1.f/256.f);
    float sq = (v0.x-mean)*(v0.x-mean)+(v0.y-mean)*(v0.y-mean)
             + (v0.z-mean)*(v0.z-mean)+(v0.w-mean)*(v0.w-mean)
             + (v1.x-mean)*(v1.x-mean)+(v1.y-mean)*(v1.y-mean)
             + (v1.z-mean)*(v1.z-mean)+(v1.w-mean)*(v1.w-mean);
    sq = wsum(sq);
    float rstd = rsqrtf(sq*(1.f/256.f) + 1e-5f);
    const float4* g4 = (const float4*)(gamma + lane*8);
    const float4* be4 = (const float4*)(beta + lane*8);
    float4 g0 = g4[0], g1 = g4[1], be0 = be4[0], be1 = be4[1];
    float4 r0, r1;
    r0.x=(v0.x-mean)*rstd*g0.x+be0.x; r0.y=(v0.y-mean)*rstd*g0.y+be0.y;
    r0.z=(v0.z-mean)*rstd*g0.z+be0.z; r0.w=(v0.w-mean)*rstd*g0.w+be0.w;
    r1.x=(v1.x-mean)*rstd*g1.x+be1.x; r1.y=(v1.y-mean)*rstd*g1.y+be1.y;
    r1.z=(v1.z-mean)*rstd*g1.z+be1.z; r1.w=(v1.w-mean)*rstd*g1.w+be1.w;
    float4* ov = (float4*)(out + (size_t)w*256 + lane*8);
    ov[0] = r0; ov[1] = r1;
}

// ---------------- host ----------------
static void launch_gemm(bool transb,
    const float* A,int lda,long long a1,long long a2,
    const float* B,int ldb,long long b1,long long b2,
    float* C,int ldc,long long c1,long long c2,
    const float* bias,int M,int Nn,int K,float alpha,int nz,int ZD)
{
    dim3 g((Nn+127)/128, (M+127)/128, nz);
    if (transb)
        gemm_tc<true><<<g,256>>>(A,lda,a1,a2,B,ldb,b1,b2,C,ldc,c1,c2,bias,Nn,K,alpha,ZD);
    else
        gemm_tc<false><<<g,256>>>(A,lda,a1,a2,B,ldb,b1,b2,C,ldc,c1,c2,bias,Nn,K,alpha,ZD);
}

extern "C" void kernel_launch(void* const* d_in, const int* in_sizes, int n_in,
                              void* d_out, int out_size)
{
    const float* x   = (const float*)d_in[0];
    const int*   ei  = (const int*)d_in[1];     // int32 (JAX default, no x64)
    const float* W1  = (const float*)d_in[3];
    const float* aS1 = (const float*)d_in[4];
    const float* aD1 = (const float*)d_in[5];
    const float* b1  = (const float*)d_in[6];
    const float* W2  = (const float*)d_in[7];
    const float* aS2 = (const float*)d_in[8];
    const float* aD2 = (const float*)d_in[9];
    const float* b2  = (const float*)d_in[10];
    const float* W3  = (const float*)d_in[11];
    const float* aS3 = (const float*)d_in[12];
    const float* aD3 = (const float*)d_in[13];
    const float* b3  = (const float*)d_in[14];
    const float* Wi  = (const float*)d_in[15];
    const float* bi  = (const float*)d_in[16];
    const float* Wo  = (const float*)d_in[17];
    const float* bo  = (const float*)d_in[18];
    const float* gam = (const float*)d_in[19];
    const float* bet = (const float*)d_in[20];
    float* out = (float*)d_out;

    float *h_, *x1_, *x2_, *qkv_, *attnO_, *att_, *x2a_, *es_, *ed_;
    int *cnt_, *rowptr_, *cursor_, *col_;
    cudaGetSymbolAddress((void**)&h_,     g_h);
    cudaGetSymbolAddress((void**)&x1_,    g_x1);
    cudaGetSymbolAddress((void**)&x2_,    g_x2);
    cudaGetSymbolAddress((void**)&qkv_,   g_qkv);
    cudaGetSymbolAddress((void**)&attnO_, g_attnO);
    cudaGetSymbolAddress((void**)&att_,   g_att);
    cudaGetSymbolAddress((void**)&x2a_,   g_x2a);
    cudaGetSymbolAddress((void**)&es_,    g_es);
    cudaGetSymbolAddress((void**)&ed_,    g_ed);
    cudaGetSymbolAddress((void**)&cnt_,   g_cnt);
    cudaGetSymbolAddress((void**)&rowptr_,g_rowptr);
    cudaGetSymbolAddress((void**)&cursor_,g_cursor);
    cudaGetSymbolAddress((void**)&col_,   g_col);

    cudaFuncSetAttribute(flash_k, cudaFuncAttributeMaxDynamicSharedMemorySize, FLASH_SMEM);

    // ---- CSR by dst ----
    init_cnt_k<<<N_NODES/256,256>>>(cnt_);
    hist_k<<<E_EDGES/256,256>>>(ei, cnt_);
    scan_k<<<1,1024>>>(cnt_, rowptr_, cursor_);
    scat_k<<<E_EDGES/256,256>>>(ei, cursor_, col_);
    selfloop_k<<<N_NODES/256,256>>>(cursor_, col_);

    const int WBLK = 4096;  // warp-per-node kernels: 8 warps/block

    // ---- GAT layer 1 ----
    launch_gemm(false, x,128,0,0, W1,256,0,0, h_,256,0,0, nullptr, N_NODES,256,128, 1.f, 1,1);
    scores4_k<<<WBLK,256>>>(h_, aS1, aD1, es_, ed_);
    agg4_k<<<WBLK,256>>>(h_, es_, ed_, rowptr_, col_, b1, x1_, 1);

    // ---- GAT layer 2 ----
    launch_gemm(false, x1_,256,0,0, W2,256,0,0, h_,256,0,0, nullptr, N_NODES,256,256, 1.f, 1,1);
    scores4_k<<<WBLK,256>>>(h_, aS2, aD2, es_, ed_);
    agg4_k<<<WBLK,256>>>(h_, es_, ed_, rowptr_, col_, b2, x2_, 1);

    // ---- MHA: QKV projection, fused flash attention, out projection ----
    launch_gemm(true,  x2_,256,0,0, Wi,256,0,0, qkv_,768,0,0, bi, N_NODES,768,256, 1.f, 1,1);
    flash_k<<<dim3(4,256),256,FLASH_SMEM>>>(qkv_, attnO_);
    launch_gemm(true,  attnO_,256,0,0, Wo,256,0,0, att_,256,0,0, bo, N_NODES,256,256, 1.f, 1,1);

    // ---- residual + LN ----
    ln_k<<<WBLK,256>>>(att_, x2_, gam, bet, x2a_);

    // ---- GAT layer 3 ----
    launch_gemm(false, x2a_,256,0,0, W3,128,0,0, h_,128,0,0, nullptr, N_NODES,128,256, 1.f, 1,1);
    scores1_k<<<WBLK,256>>>(h_, aS3, aD3, es_, ed_);
    agg1_k<<<WBLK,256>>>(h_, es_, ed_, rowptr_, col_, b3, out);
}